// round 2
// baseline (speedup 1.0000x reference)
#include <cuda_runtime.h>

// DeconvCapsuleLayer fused kernel, round 2: packed fma.rn.f32x2 mainloop.
//   conv2d_transpose (k=4, s=2, SAME, TF transpose_kernel semantics)
//   + 3-iteration capsule routing, fully fused (votes never hit HBM).
//
// Reference quirk reproduced: conv batch is Cin-major ([Cin*B,...]) but votes
// are reshaped (B, Cin, ...), so route i of output batch b uses input
// (bb, cin) = ((8b+i)&3, (8b+i)>>2).
//
// f32x2 packing: packed dim = output column pair (ca pairs). The broadcast
// x scalar is pre-DUPLICATED in shared memory at gather time, so the hot
// loop is pure {LDG.128 weights, LDS.128 dup'd x, FFMA2} with no packing ALU.

namespace {
constexpr int HIN = 56, WIN = 56, CIN = 8, AIN = 32;
constexpr int HP = 112, WP = 112;
constexpr int CA = 128;   // Cout(8) * Aout(16)
constexpr int KD = 128;   // 4 taps * 32 ain
}

typedef unsigned long long u64;

// Per-parity-class weights: [class(4)][k = tap*32+ain (128)][ca (128)]
__device__ float g_Wc[4 * KD * CA];

__global__ void prep_weights_kernel(const float* __restrict__ W) {
    int idx = blockIdx.x * blockDim.x + threadIdx.x;
    if (idx >= 4 * KD * CA) return;
    int ca   = idx & 127;
    int k    = (idx >> 7) & 127;
    int cls  = idx >> 14;
    int t    = k >> 5;       // tap = pp*2 + qq
    int ain  = k & 31;
    int hpar = cls >> 1, wpar = cls & 1;
    int p = (1 - hpar) + 2 * (t >> 1);
    int q = (1 - wpar) + 2 * (t & 1);
    // W layout: [p(4)][q(4)][ca(128)][ain(32)]
    g_Wc[idx] = W[((p * 4 + q) * CA + ca) * AIN + ain];
}

__device__ __forceinline__ void fma2(u64& d, u64 a, u64 b) {
    asm("fma.rn.f32x2 %0, %1, %2, %0;" : "+l"(d) : "l"(a), "l"(b));
}
__device__ __forceinline__ void ldg_v2b64(u64& a, u64& b, const void* p) {
    asm("ld.global.nc.v2.b64 {%0,%1}, [%2];" : "=l"(a), "=l"(b) : "l"(p));
}
__device__ __forceinline__ void lds_v2b64(u64& a, u64& b, const void* p) {
    unsigned sp = (unsigned)__cvta_generic_to_shared(p);
    asm("ld.shared.v2.b64 {%0,%1}, [%2];" : "=l"(a), "=l"(b) : "r"(sp));
}
__device__ __forceinline__ float lo32(u64 v) { return __uint_as_float((unsigned)v); }
__device__ __forceinline__ float hi32(u64 v) { return __uint_as_float((unsigned)(v >> 32)); }

__global__ void __launch_bounds__(128)
deconv_caps_kernel(const float* __restrict__ x,
                   const float* __restrict__ bias,
                   float* __restrict__ out)
{
    // One warp = one output pixel. 4 warps/block.
    // Per warp: [route(8)][k(128) duplicated x2] floats = 8 KB.
    __shared__ float Xsh[4 * 2048];

    const int lane = threadIdx.x & 31;
    const int warp = threadIdx.x >> 5;
    const int h    = blockIdx.y;
    const int b    = blockIdx.z;
    const int wpar = blockIdx.x & 1;
    const int wblk = blockIdx.x >> 1;
    const int w    = wpar + 2 * (wblk * 4 + warp);      // 0..111, parity = wpar
    const int cls  = (h & 1) * 2 + wpar;
    const int ih   = (h + 1) >> 1;
    const int jw   = (w + 1) >> 1;

    float4* Xw4 = (float4*)(Xsh + warp * 2048);   // 8 routes * 64 float4

    // ---- gather x, writing each scalar DUPLICATED: (s,s) pairs, k-major.
    // lane's float4 covers k = 4*lane .. 4*lane+3 of its route row.
    {
        const int t  = lane >> 3;          // tap for this lane
        const int ii = ih - (t >> 1);
        const int jj = jw - (t & 1);
        const bool valid = ((unsigned)ii < (unsigned)HIN) && ((unsigned)jj < (unsigned)WIN);
        #pragma unroll
        for (int r = 0; r < 8; ++r) {
            int n   = b * 8 + r;           // reference reshape quirk
            int bb  = n & 3;
            int cin = n >> 2;
            float4 v = make_float4(0.f, 0.f, 0.f, 0.f);
            if (valid) {
                const float4* src = (const float4*)x
                    + ((((bb * HIN + ii) * WIN + jj) * CIN + cin) * AIN >> 2);
                v = __ldg(src + (lane & 7));
            }
            Xw4[r * 64 + 2 * lane + 0] = make_float4(v.x, v.x, v.y, v.y);
            Xw4[r * 64 + 2 * lane + 1] = make_float4(v.z, v.z, v.w, v.w);
        }
    }
    __syncwarp();

    // ---- votes GEMM with packed f32x2.
    // lane owns columns ca = 4*lane + {0..3}; accp[i][0]=(c0,c1), accp[i][1]=(c2,c3).
    u64 accp[8][2];
    #pragma unroll
    for (int i = 0; i < 8; ++i) { accp[i][0] = 0ull; accp[i][1] = 0ull; }

    const char* __restrict__ Wb = (const char*)(g_Wc + cls * (KD * CA));
    #pragma unroll 2
    for (int k4 = 0; k4 < 32; ++k4) {
        u64 wv[8];                          // 4 k-steps * 2 column-pairs
        #pragma unroll
        for (int kk = 0; kk < 4; ++kk)
            ldg_v2b64(wv[2 * kk], wv[2 * kk + 1],
                      Wb + (size_t)((k4 * 4 + kk) * 32 + lane) * 16);
        #pragma unroll
        for (int i = 0; i < 8; ++i) {
            u64 x0, x1, x2, x3;             // dup'd scalars for k=4k4..4k4+3
            const float4* xp = Xw4 + (i * 64 + 2 * k4);
            lds_v2b64(x0, x1, xp);
            lds_v2b64(x2, x3, xp + 1);
            fma2(accp[i][0], x0, wv[0]);
            fma2(accp[i][1], x0, wv[1]);
            fma2(accp[i][0], x1, wv[2]);
            fma2(accp[i][1], x1, wv[3]);
            fma2(accp[i][0], x2, wv[4]);
            fma2(accp[i][1], x2, wv[5]);
            fma2(accp[i][0], x3, wv[6]);
            fma2(accp[i][1], x3, wv[7]);
        }
    }

    // unpack accumulators for routing
    float acc[8][4];
    #pragma unroll
    for (int i = 0; i < 8; ++i) {
        acc[i][0] = lo32(accp[i][0]); acc[i][1] = hi32(accp[i][0]);
        acc[i][2] = lo32(accp[i][1]); acc[i][3] = hi32(accp[i][1]);
    }

    // ---- routing (3 iterations), registers + shuffles.
    // lane's 4 columns all belong to cout c = lane>>2; a = 4*(lane&3)+j.
    const float4 bs = __ldg((const float4*)bias + lane);

    float logits[8];
    #pragma unroll
    for (int i = 0; i < 8; ++i) logits[i] = 0.f;

    float a0 = 0.f, a1 = 0.f, a2 = 0.f, a3 = 0.f;

    #pragma unroll
    for (int it = 0; it < 3; ++it) {
        // softmax over the 8 couts (xor {4,8,16} reduces exactly over cout)
        float r[8];
        #pragma unroll
        for (int i = 0; i < 8; ++i) {
            float m = logits[i];
            m = fmaxf(m, __shfl_xor_sync(0xffffffffu, m, 4));
            m = fmaxf(m, __shfl_xor_sync(0xffffffffu, m, 8));
            m = fmaxf(m, __shfl_xor_sync(0xffffffffu, m, 16));
            float e = expf(logits[i] - m);
            float s = e;
            s += __shfl_xor_sync(0xffffffffu, s, 4);
            s += __shfl_xor_sync(0xffffffffu, s, 8);
            s += __shfl_xor_sync(0xffffffffu, s, 16);
            r[i] = e / s;
        }
        // pre = bias + sum_i r[i]*votes[i]
        float p0 = bs.x, p1 = bs.y, p2 = bs.z, p3 = bs.w;
        #pragma unroll
        for (int i = 0; i < 8; ++i) {
            p0 = fmaf(r[i], acc[i][0], p0);
            p1 = fmaf(r[i], acc[i][1], p1);
            p2 = fmaf(r[i], acc[i][2], p2);
            p3 = fmaf(r[i], acc[i][3], p3);
        }
        // squash: norm over 16 atoms of this cout (xor {1,2} over a-group)
        float sq = p0 * p0 + p1 * p1 + p2 * p2 + p3 * p3;
        sq += __shfl_xor_sync(0xffffffffu, sq, 1);
        sq += __shfl_xor_sync(0xffffffffu, sq, 2);
        float scale = sq / ((1.0f + sq) * sqrtf(sq + 1e-9f));
        a0 = p0 * scale; a1 = p1 * scale; a2 = p2 * scale; a3 = p3 * scale;

        if (it < 2) {
            #pragma unroll
            for (int i = 0; i < 8; ++i) {
                float d = acc[i][0] * a0 + acc[i][1] * a1
                        + acc[i][2] * a2 + acc[i][3] * a3;
                d += __shfl_xor_sync(0xffffffffu, d, 1);
                d += __shfl_xor_sync(0xffffffffu, d, 2);
                logits[i] += d;
            }
        }
    }

    // ---- write act: out[b,h,w,ca], float4 per lane (coalesced 512B per warp)
    ((float4*)out)[(size_t)((b * HP + h) * WP + w) * 32 + lane]
        = make_float4(a0, a1, a2, a3);
}

extern "C" void kernel_launch(void* const* d_in, const int* in_sizes, int n_in,
                              void* d_out, int out_size) {
    const float* x = nullptr;
    const float* W = nullptr;
    const float* bias = nullptr;
    for (int i = 0; i < n_in; ++i) {
        if (in_sizes[i] == 4 * 56 * 56 * 8 * 32) x    = (const float*)d_in[i];
        else if (in_sizes[i] == 4 * 4 * 128 * 32) W   = (const float*)d_in[i];
        else if (in_sizes[i] == 128)              bias = (const float*)d_in[i];
    }
    float* out = (float*)d_out;

    prep_weights_kernel<<<(4 * KD * CA + 255) / 256, 256>>>(W);

    // grid: x = (wblk(14) * 2 + wpar) = 28, y = h (112), z = b (4)
    dim3 grid(28, HP, 4);
    deconv_caps_kernel<<<grid, 128>>>(x, bias, out);
}

// round 4
// speedup vs baseline: 1.1562x; 1.1562x over previous
#include <cuda_runtime.h>
#include <cuda_bf16.h>
#include <cstdint>

// DeconvCapsuleLayer, round 4: ldmatrix + mma.sync.m16n8k16 bf16 (legacy HMMA,
// compiles for baseline compute_103) with 3-term bf16 split for fp32 accuracy:
//   D = A_hi*B_hi + A_hi*B_lo + A_lo*B_hi   (dropped A_lo*B_lo ~ 2^-16 rel)
// Fused with 3-iteration capsule routing (votes never hit HBM).
//
// Per parity class (h%2,w%2): tile = 16 output pixels -> GEMM M=128 (pix*route),
// N=128 (ca), K=128 (4 taps * 32 ain). Block = 256 thr (8 warps, 32x64 each).
//
// Reference quirk reproduced: route i of output batch b uses input
// (bb, cin) = ((8b+i)&3, (8b+i)>>2).

namespace {
constexpr int HIN = 56, WIN = 56, CIN = 8, AIN = 32;
constexpr int HP = 112, WP = 112;
// SMEM map (bytes): A_hi 32K | A_lo 32K | B_hi 32K | B_lo 32K.  D (128x128 f32,
// pitch 512B, swizzled) overlays the B region after the mainloop.
constexpr int SM_AHI = 0;
constexpr int SM_ALO = 32768;
constexpr int SM_BHI = 65536;
constexpr int SM_BLO = 98304;
constexpr int SM_D   = SM_BHI;
constexpr int SMEM_TOTAL = 131072;
}

// Pre-split, pre-swizzled B: [cls(4)][split(2)][n(128)][k(128)] bf16.
// Swizzle within each [n][k] plane: off = n*256 + k*2; sw = off ^ ((n&7)<<4).
__device__ __nv_bfloat16 g_B[4 * 2 * 128 * 128];

__global__ void prep_B_kernel(const float* __restrict__ W) {
    int idx = blockIdx.x * blockDim.x + threadIdx.x;
    if (idx >= 4 * 2 * 128 * 128) return;
    int k   = idx & 127;
    int n   = (idx >> 7) & 127;
    int sp  = (idx >> 14) & 1;
    int cls = idx >> 15;
    int t = k >> 5, ain = k & 31;
    int hpar = cls >> 1, wpar = cls & 1;
    int p = (1 - hpar) + 2 * (t >> 1);
    int q = (1 - wpar) + 2 * (t & 1);
    float wv = W[((p * 4 + q) * 128 + n) * AIN + ain];
    __nv_bfloat16 hi = __float2bfloat16(wv);
    __nv_bfloat16 val = (sp == 0) ? hi
                      : __float2bfloat16(wv - __bfloat162float(hi));
    uint32_t off = (uint32_t)(n * 256) + (((uint32_t)(k * 2)) ^ ((uint32_t)(n & 7) << 4));
    *(__nv_bfloat16*)((char*)g_B + (((size_t)(cls * 2 + sp)) << 15) + off) = val;
}

__device__ __forceinline__ void ldm_x4(uint32_t* r, uint32_t addr) {
    asm volatile("ldmatrix.sync.aligned.m8n8.x4.shared.b16 {%0,%1,%2,%3}, [%4];"
                 : "=r"(r[0]), "=r"(r[1]), "=r"(r[2]), "=r"(r[3]) : "r"(addr));
}
__device__ __forceinline__ void mma_bf16(float* d, const uint32_t* a, const uint32_t* b) {
    asm volatile("mma.sync.aligned.m16n8k16.row.col.f32.bf16.bf16.f32 "
                 "{%0,%1,%2,%3}, {%4,%5,%6,%7}, {%8,%9}, {%0,%1,%2,%3};"
                 : "+f"(d[0]), "+f"(d[1]), "+f"(d[2]), "+f"(d[3])
                 : "r"(a[0]), "r"(a[1]), "r"(a[2]), "r"(a[3]), "r"(b[0]), "r"(b[1]));
}
__device__ __forceinline__ uint32_t pack_bf2(float a, float b) {
    __nv_bfloat162 v;
    v.x = __float2bfloat16(a);
    v.y = __float2bfloat16(b);
    return *(uint32_t*)&v;
}

__global__ void __launch_bounds__(256, 1)
deconv_caps_mma_kernel(const float* __restrict__ x,
                       const float* __restrict__ bias,
                       float* __restrict__ out)
{
    extern __shared__ char smem[];
    const uint32_t sbase = (uint32_t)__cvta_generic_to_shared(smem);
    const int tid  = threadIdx.x;
    const int lane = tid & 31;
    const int wid  = tid >> 5;
    const int cls  = blockIdx.y;
    const int tile = blockIdx.x;
    const int hpar = cls >> 1, wpar = cls & 1;

    // ---- copy pre-swizzled B (hi+lo, 64KB) for this class
    {
        const float4* src = (const float4*)((const char*)g_B + ((size_t)cls << 16));
        float4* dst = (float4*)(smem + SM_BHI);
        #pragma unroll
        for (int i = 0; i < 16; ++i)
            dst[tid + 256 * i] = __ldg(src + tid + 256 * i);
    }

    // ---- gather A: row m = tid>>1 (pixel*8+route), k-half = tid&1 (2 taps)
    {
        const int m = tid >> 1, half = tid & 1;
        const int p = m >> 3, route = m & 7;
        const int P   = tile * 16 + p;
        const int b   = P / 3136;
        const int rem = P - b * 3136;
        const int hh  = rem / 56, ww = rem - (rem / 56) * 56;
        const int h   = hpar + 2 * hh;
        const int w   = wpar + 2 * ww;
        const int ih  = (h + 1) >> 1, jw = (w + 1) >> 1;
        const int n   = b * 8 + route;          // reference reshape quirk
        const int bb  = n & 3, cin = n >> 2;
        const uint32_t rx = (uint32_t)(m & 7) << 4;
        char* Ahi = smem + SM_AHI + m * 256;
        char* Alo = smem + SM_ALO + m * 256;

        #pragma unroll
        for (int tt = 0; tt < 2; ++tt) {
            const int t  = half * 2 + tt;
            const int ii = ih - (t >> 1);
            const int jj = jw - (t & 1);
            const bool valid = ((unsigned)ii < (unsigned)HIN) && ((unsigned)jj < (unsigned)WIN);
            const float4* src = (const float4*)x
                + ((size_t)(((bb * HIN + ii) * WIN + jj) * CIN + cin) * AIN >> 2);
            #pragma unroll
            for (int q = 0; q < 8; ++q) {
                float4 v = valid ? __ldg(src + q) : make_float4(0.f, 0.f, 0.f, 0.f);
                uint32_t h0 = pack_bf2(v.x, v.y);
                uint32_t h1 = pack_bf2(v.z, v.w);
                // residuals (exact in fp32)
                __nv_bfloat162 hv0 = *(__nv_bfloat162*)&h0;
                __nv_bfloat162 hv1 = *(__nv_bfloat162*)&h1;
                uint32_t l0 = pack_bf2(v.x - __bfloat162float(hv0.x),
                                       v.y - __bfloat162float(hv0.y));
                uint32_t l1 = pack_bf2(v.z - __bfloat162float(hv1.x),
                                       v.w - __bfloat162float(hv1.y));
                uint32_t kb = (uint32_t)(t * 64 + q * 8);
                uint32_t offk = kb ^ rx;
                *(uint2*)(Ahi + offk) = make_uint2(h0, h1);
                *(uint2*)(Alo + offk) = make_uint2(l0, l1);
            }
        }
    }
    __syncthreads();

    // ---- mainloop: warp (wid) computes rows mb..mb+31, cols nbase..nbase+63
    const int mb    = (wid & 3) * 32;
    const int nbase = (wid >> 2) * 64;

    float d[2][8][4];
    #pragma unroll
    for (int mi = 0; mi < 2; ++mi)
        #pragma unroll
        for (int nt = 0; nt < 8; ++nt)
            #pragma unroll
            for (int j = 0; j < 4; ++j) d[mi][nt][j] = 0.f;

    // ldmatrix lane address components (swizzle XOR constants per lane)
    const int ar = lane & 15;
    const uint32_t rowA0 = (uint32_t)((mb + ar) * 256);
    const uint32_t rowA1 = (uint32_t)((mb + 16 + ar) * 256);
    const uint32_t a_kl  = (uint32_t)((lane >> 4) << 4);
    const uint32_t rxA   = (uint32_t)(ar & 7) << 4;

    const int brr = (lane & 7) + ((lane >> 4) << 3);
    uint32_t rowB[4];
    #pragma unroll
    for (int nt = 0; nt < 4; ++nt)
        rowB[nt] = (uint32_t)((nbase + nt * 16 + brr) * 256);
    const uint32_t b_kl = (uint32_t)(((lane >> 3) & 1) << 4);
    const uint32_t rxB  = (uint32_t)(lane & 7) << 4;

    #pragma unroll
    for (int s = 0; s < 3; ++s) {
        const uint32_t Ab = sbase + (s < 2 ? SM_AHI : SM_ALO);
        const uint32_t Bb = sbase + (s == 1 ? SM_BLO : SM_BHI);
        #pragma unroll
        for (int k0 = 0; k0 < 128; k0 += 16) {
            const uint32_t ka = ((uint32_t)(k0 * 2) + a_kl) ^ rxA;
            const uint32_t kb = ((uint32_t)(k0 * 2) + b_kl) ^ rxB;
            uint32_t a[2][4];
            ldm_x4(a[0], Ab + rowA0 + ka);
            ldm_x4(a[1], Ab + rowA1 + ka);
            #pragma unroll
            for (int nt = 0; nt < 4; ++nt) {
                uint32_t bf[4];
                ldm_x4(bf, Bb + rowB[nt] + kb);
                #pragma unroll
                for (int mi = 0; mi < 2; ++mi) {
                    mma_bf16(d[mi][nt * 2 + 0], a[mi], bf + 0);
                    mma_bf16(d[mi][nt * 2 + 1], a[mi], bf + 2);
                }
            }
        }
    }

    // ---- stage D into SMEM (overlay B region), pitch 512B, swizzled
    __syncthreads();   // all ldmatrix B reads done before overwrite
    {
        const int g  = lane >> 2;
        const int c2 = (lane & 3) * 2;
        #pragma unroll
        for (int mi = 0; mi < 2; ++mi) {
            #pragma unroll
            for (int nt = 0; nt < 8; ++nt) {
                const int col = nbase + nt * 8 + c2;
                const int r0  = mb + mi * 16 + g;
                const uint32_t cb = (uint32_t)(col * 4);
                uint32_t o0 = (uint32_t)(r0 * 512) + (cb ^ ((uint32_t)(r0 & 7) << 4));
                uint32_t o1 = (uint32_t)((r0 + 8) * 512) + (cb ^ ((uint32_t)((r0 + 8) & 7) << 4));
                *(float2*)(smem + SM_D + o0) = make_float2(d[mi][nt][0], d[mi][nt][1]);
                *(float2*)(smem + SM_D + o1) = make_float2(d[mi][nt][2], d[mi][nt][3]);
            }
        }
    }
    __syncthreads();

    // ---- routing: warp handles 2 pixels; lane owns ca = 4*lane+{0..3}
    const float4 bs = __ldg((const float4*)bias + lane);

    #pragma unroll 1
    for (int pp = 0; pp < 2; ++pp) {
        const int p = wid * 2 + pp;
        float acc[8][4];
        #pragma unroll
        for (int i = 0; i < 8; ++i) {
            const int row = p * 8 + i;
            uint32_t off = (uint32_t)(row * 512)
                         + (((uint32_t)(lane * 16)) ^ ((uint32_t)(row & 7) << 4));
            float4 v = *(const float4*)(smem + SM_D + off);
            acc[i][0] = v.x; acc[i][1] = v.y; acc[i][2] = v.z; acc[i][3] = v.w;
        }

        float logits[8];
        #pragma unroll
        for (int i = 0; i < 8; ++i) logits[i] = 0.f;
        float a0 = 0.f, a1 = 0.f, a2 = 0.f, a3 = 0.f;

        #pragma unroll
        for (int it = 0; it < 3; ++it) {
            float r[8];
            #pragma unroll
            for (int i = 0; i < 8; ++i) {
                float m = logits[i];
                m = fmaxf(m, __shfl_xor_sync(0xffffffffu, m, 4));
                m = fmaxf(m, __shfl_xor_sync(0xffffffffu, m, 8));
                m = fmaxf(m, __shfl_xor_sync(0xffffffffu, m, 16));
                float e = expf(logits[i] - m);
                float s = e;
                s += __shfl_xor_sync(0xffffffffu, s, 4);
                s += __shfl_xor_sync(0xffffffffu, s, 8);
                s += __shfl_xor_sync(0xffffffffu, s, 16);
                r[i] = e / s;
            }
            float p0 = bs.x, p1 = bs.y, p2 = bs.z, p3 = bs.w;
            #pragma unroll
            for (int i = 0; i < 8; ++i) {
                p0 = fmaf(r[i], acc[i][0], p0);
                p1 = fmaf(r[i], acc[i][1], p1);
                p2 = fmaf(r[i], acc[i][2], p2);
                p3 = fmaf(r[i], acc[i][3], p3);
            }
            float sq = p0 * p0 + p1 * p1 + p2 * p2 + p3 * p3;
            sq += __shfl_xor_sync(0xffffffffu, sq, 1);
            sq += __shfl_xor_sync(0xffffffffu, sq, 2);
            float scale = sq / ((1.0f + sq) * sqrtf(sq + 1e-9f));
            a0 = p0 * scale; a1 = p1 * scale; a2 = p2 * scale; a3 = p3 * scale;

            if (it < 2) {
                #pragma unroll
                for (int i = 0; i < 8; ++i) {
                    float dd = acc[i][0] * a0 + acc[i][1] * a1
                             + acc[i][2] * a2 + acc[i][3] * a3;
                    dd += __shfl_xor_sync(0xffffffffu, dd, 1);
                    dd += __shfl_xor_sync(0xffffffffu, dd, 2);
                    logits[i] += dd;
                }
            }
        }

        const int P   = tile * 16 + p;
        const int b   = P / 3136;
        const int rem = P - b * 3136;
        const int hh  = rem / 56, ww = rem - (rem / 56) * 56;
        const int h   = hpar + 2 * hh;
        const int w   = wpar + 2 * ww;
        ((float4*)out)[(size_t)((b * HP + h) * WP + w) * 32 + lane]
            = make_float4(a0, a1, a2, a3);
    }
}

extern "C" void kernel_launch(void* const* d_in, const int* in_sizes, int n_in,
                              void* d_out, int out_size) {
    const float* x = nullptr;
    const float* W = nullptr;
    const float* bias = nullptr;
    for (int i = 0; i < n_in; ++i) {
        if (in_sizes[i] == 4 * 56 * 56 * 8 * 32) x    = (const float*)d_in[i];
        else if (in_sizes[i] == 4 * 4 * 128 * 32) W   = (const float*)d_in[i];
        else if (in_sizes[i] == 128)              bias = (const float*)d_in[i];
    }
    float* out = (float*)d_out;

    cudaFuncSetAttribute(deconv_caps_mma_kernel,
                         cudaFuncAttributeMaxDynamicSharedMemorySize, SMEM_TOTAL);

    prep_B_kernel<<<(4 * 2 * 128 * 128 + 255) / 256, 256>>>(W);

    dim3 grid(784, 4);
    deconv_caps_mma_kernel<<<grid, 256, SMEM_TOTAL>>>(x, bias, out);
}

// round 5
// speedup vs baseline: 1.1653x; 1.0079x over previous
#include <cuda_runtime.h>
#include <cuda_bf16.h>
#include <cstdint>

// DeconvCapsuleLayer, round 5: persistent blocks + cp.async-pipelined gather.
//   - mma.sync.m16n8k16 bf16, 3-term split (hi*hi + hi*lo + lo*hi) ~ fp32.
//   - x pre-split to bf16 hi/lo in GMEM; A gather = pure cp.async (zfill OOB).
//   - B (per class, pre-swizzled) loaded once per block, resident across tiles.
//   - Double-buffered A: gather(t+1) overlaps mainloop(t). D overlays A(t).
//
// Reference quirk reproduced: route i of output batch b uses input
// (bb, cin) = ((8b+i)&3, (8b+i)>>2).

namespace {
constexpr int HIN = 56, WIN = 56, CIN = 8, AIN = 32;
constexpr int HP = 112, WP = 112;
constexpr int XN = 4 * 56 * 56 * 8 * 32;     // elements in x
// SMEM map: B 64KB (hi 32K + lo 32K) | Abuf0 64KB (hi+lo) | Abuf1 64KB
constexpr int SM_B  = 0;
constexpr int SM_A0 = 65536;
constexpr int SM_A1 = 131072;
constexpr int SMEM_TOTAL = 196608;
constexpr int NBLK = 37;                     // blocks per class (37*4 = 148)
}

// Pre-split, pre-swizzled B: [cls(4)][split(2)][n(128)][k(128)] bf16.
__device__ __nv_bfloat16 g_B[4 * 2 * 128 * 128];
// Pre-split x: [split(2)][bb][ii][jj][cin][ain] bf16
__device__ __nv_bfloat16 g_xs[2 * XN];

__global__ void prep_B_kernel(const float* __restrict__ W) {
    int idx = blockIdx.x * blockDim.x + threadIdx.x;
    if (idx >= 4 * 2 * 128 * 128) return;
    int k   = idx & 127;
    int n   = (idx >> 7) & 127;
    int sp  = (idx >> 14) & 1;
    int cls = idx >> 15;
    int t = k >> 5, ain = k & 31;
    int hpar = cls >> 1, wpar = cls & 1;
    int p = (1 - hpar) + 2 * (t >> 1);
    int q = (1 - wpar) + 2 * (t & 1);
    float wv = W[((p * 4 + q) * 128 + n) * AIN + ain];
    __nv_bfloat16 hi = __float2bfloat16(wv);
    __nv_bfloat16 val = (sp == 0) ? hi
                      : __float2bfloat16(wv - __bfloat162float(hi));
    uint32_t off = (uint32_t)(n * 256) + (((uint32_t)(k * 2)) ^ ((uint32_t)(n & 7) << 4));
    *(__nv_bfloat16*)((char*)g_B + (((size_t)(cls * 2 + sp)) << 15) + off) = val;
}

__global__ void prep_x_kernel(const float* __restrict__ x) {
    int idx = blockIdx.x * blockDim.x + threadIdx.x;
    if (idx >= XN) return;
    float v = x[idx];
    __nv_bfloat16 hi = __float2bfloat16(v);
    g_xs[idx]      = hi;
    g_xs[XN + idx] = __float2bfloat16(v - __bfloat162float(hi));
}

// ---------------- PTX helpers ----------------
__device__ __forceinline__ void cpa16(uint32_t dst, const void* src, uint32_t srcsize) {
    asm volatile("cp.async.cg.shared.global [%0], [%1], 16, %2;"
                 :: "r"(dst), "l"(src), "r"(srcsize) : "memory");
}
__device__ __forceinline__ void cpa_commit() {
    asm volatile("cp.async.commit_group;" ::: "memory");
}
__device__ __forceinline__ void ldm_x4(uint32_t* r, uint32_t addr) {
    asm volatile("ldmatrix.sync.aligned.m8n8.x4.shared.b16 {%0,%1,%2,%3}, [%4];"
                 : "=r"(r[0]), "=r"(r[1]), "=r"(r[2]), "=r"(r[3]) : "r"(addr));
}
__device__ __forceinline__ void mma_bf16(float* d, const uint32_t* a, const uint32_t* b) {
    asm volatile("mma.sync.aligned.m16n8k16.row.col.f32.bf16.bf16.f32 "
                 "{%0,%1,%2,%3}, {%4,%5,%6,%7}, {%8,%9}, {%0,%1,%2,%3};"
                 : "+f"(d[0]), "+f"(d[1]), "+f"(d[2]), "+f"(d[3])
                 : "r"(a[0]), "r"(a[1]), "r"(a[2]), "r"(a[3]), "r"(b[0]), "r"(b[1]));
}

__global__ void __launch_bounds__(256, 1)
deconv_caps_pers_kernel(const float* __restrict__ bias,
                        float* __restrict__ out)
{
    extern __shared__ char smem[];
    const uint32_t sbase = (uint32_t)__cvta_generic_to_shared(smem);
    const int tid  = threadIdx.x;
    const int lane = tid & 31;
    const int wid  = tid >> 5;
    const int cls  = blockIdx.y;
    const int blk  = blockIdx.x;
    const int hpar = cls >> 1, wpar = cls & 1;

    // tile range: 784 tiles over 37 blocks -> first 7 blocks get 22, rest 21
    const int base = blk * 21 + (blk < 7 ? blk : 7);
    const int cnt  = 21 + (blk < 7 ? 1 : 0);

    // ---- issue B copy (pre-swizzled, 64KB) via cp.async : group 0
    {
        const char* Bsrc = (const char*)g_B + ((size_t)cls << 16);
        #pragma unroll
        for (int i = 0; i < 16; ++i) {
            uint32_t o = (uint32_t)(tid + 256 * i) * 16;
            cpa16(sbase + SM_B + o, Bsrc + o, 16);
        }
        cpa_commit();
    }

    // ---- per-thread gather constants: row m = tid>>1, k-half = tid&1
    const int m = tid >> 1, half = tid & 1;
    const int mypix = m >> 3, route = m & 7;
    const int n_r  = route;                    // route in 0..7 (b added per tile)
    const uint32_t rx_m = (uint32_t)(m & 7) << 4;

    // gather lambda (cp.async only)
    auto gather = [&](int T, uint32_t abuf) {
        const int P   = T * 16 + mypix;
        const int b   = P / 3136;
        const int rem = P - b * 3136;
        const int hh  = rem / 56, ww = rem - (rem / 56) * 56;
        const int h   = hpar + 2 * hh;
        const int w   = wpar + 2 * ww;
        const int ih  = (h + 1) >> 1, jw = (w + 1) >> 1;
        const int nn  = b * 8 + n_r;           // reference reshape quirk
        const int bb  = nn & 3, cin = nn >> 2;
        #pragma unroll
        for (int tt = 0; tt < 2; ++tt) {
            const int t  = half * 2 + tt;
            const int ii = ih - (t >> 1);
            const int jj = jw - (t & 1);
            const bool valid = ((unsigned)ii < (unsigned)HIN) && ((unsigned)jj < (unsigned)WIN);
            const int iic = valid ? ii : 0, jjc = valid ? jj : 0;
            const uint32_t ssz = valid ? 16u : 0u;
            const char* shi = (const char*)(g_xs
                + (size_t)(((bb * HIN + iic) * WIN + jjc) * CIN + cin) * AIN);
            #pragma unroll
            for (int c = 0; c < 4; ++c) {
                const uint32_t cb  = (uint32_t)(t * 4 + c);
                const uint32_t dof = (uint32_t)m * 256 + ((cb << 4) ^ rx_m);
                cpa16(abuf + dof,         shi + c * 16,               ssz);
                cpa16(abuf + 32768 + dof, shi + (size_t)XN * 2 + c * 16, ssz);
            }
        }
        cpa_commit();
    };

    // ---- prologue: gather tile 0 : group 1
    gather(base, sbase + SM_A0);

    // ---- mainloop constants (warp tile: rows mb..mb+31, cols nbase..nbase+63)
    const int mb    = (wid & 3) * 32;
    const int nbase = (wid >> 2) * 64;
    const int ar = lane & 15;
    const uint32_t rowA0 = (uint32_t)((mb + ar) * 256);
    const uint32_t rowA1 = (uint32_t)((mb + 16 + ar) * 256);
    const uint32_t a_kl  = (uint32_t)((lane >> 4) << 4);
    const uint32_t rxA   = (uint32_t)(ar & 7) << 4;
    const int brr = (lane & 7) + ((lane >> 4) << 3);
    uint32_t rowB[4];
    #pragma unroll
    for (int nt = 0; nt < 4; ++nt)
        rowB[nt] = (uint32_t)((nbase + nt * 16 + brr) * 256);
    const uint32_t b_kl = (uint32_t)(((lane >> 3) & 1) << 4);
    const uint32_t rxB  = (uint32_t)(lane & 7) << 4;

    const float4 bs = __ldg((const float4*)bias + lane);

    #pragma unroll 1
    for (int it = 0; it < cnt; ++it) {
        const uint32_t acur = sbase + ((it & 1) ? SM_A1 : SM_A0);
        const bool pre = (it + 1 < cnt);
        if (pre) gather(base + it + 1, sbase + (((it + 1) & 1) ? SM_A1 : SM_A0));

        // wait for A(it) (and B on first iter); newest group (prefetch) may fly
        if (pre) asm volatile("cp.async.wait_group 1;" ::: "memory");
        else     asm volatile("cp.async.wait_group 0;" ::: "memory");
        __syncthreads();

        // ---- mainloop: 3 splits x 8 k-steps
        float d[2][8][4];
        #pragma unroll
        for (int mi = 0; mi < 2; ++mi)
            #pragma unroll
            for (int nt = 0; nt < 8; ++nt)
                #pragma unroll
                for (int j = 0; j < 4; ++j) d[mi][nt][j] = 0.f;

        #pragma unroll
        for (int s = 0; s < 3; ++s) {
            const uint32_t Ab = acur + (s < 2 ? 0 : 32768);
            const uint32_t Bb = sbase + SM_B + (s == 1 ? 32768 : 0);
            #pragma unroll
            for (int k0 = 0; k0 < 128; k0 += 16) {
                const uint32_t ka = ((uint32_t)(k0 * 2) + a_kl) ^ rxA;
                const uint32_t kb = ((uint32_t)(k0 * 2) + b_kl) ^ rxB;
                uint32_t a[2][4];
                ldm_x4(a[0], Ab + rowA0 + ka);
                ldm_x4(a[1], Ab + rowA1 + ka);
                #pragma unroll
                for (int nt = 0; nt < 4; ++nt) {
                    uint32_t bf[4];
                    ldm_x4(bf, Bb + rowB[nt] + kb);
                    #pragma unroll
                    for (int mi = 0; mi < 2; ++mi) {
                        mma_bf16(d[mi][nt * 2 + 0], a[mi], bf + 0);
                        mma_bf16(d[mi][nt * 2 + 1], a[mi], bf + 2);
                    }
                }
            }
        }
        __syncthreads();   // all ldmatrix A reads done before D overlays acur

        // ---- stage D into acur (pitch 512B, swizzled)
        {
            const int g  = lane >> 2;
            const int c2 = (lane & 3) * 2;
            #pragma unroll
            for (int mi = 0; mi < 2; ++mi) {
                #pragma unroll
                for (int nt = 0; nt < 8; ++nt) {
                    const int col = nbase + nt * 8 + c2;
                    const int r0  = mb + mi * 16 + g;
                    const uint32_t cb = (uint32_t)(col * 4);
                    uint32_t o0 = (uint32_t)(r0 * 512) + (cb ^ ((uint32_t)(r0 & 7) << 4));
                    uint32_t o1 = (uint32_t)((r0 + 8) * 512) + (cb ^ ((uint32_t)((r0 + 8) & 7) << 4));
                    char* Dp = smem + (acur - sbase);
                    *(float2*)(Dp + o0) = make_float2(d[mi][nt][0], d[mi][nt][1]);
                    *(float2*)(Dp + o1) = make_float2(d[mi][nt][2], d[mi][nt][3]);
                }
            }
        }
        __syncthreads();

        // ---- routing: warp handles 2 pixels; lane owns ca = 4*lane+{0..3}
        const char* Dp = smem + (acur - sbase);
        #pragma unroll 1
        for (int pp = 0; pp < 2; ++pp) {
            const int p = wid * 2 + pp;
            float acc[8][4];
            #pragma unroll
            for (int i = 0; i < 8; ++i) {
                const int row = p * 8 + i;
                uint32_t off = (uint32_t)(row * 512)
                             + (((uint32_t)(lane * 16)) ^ ((uint32_t)(row & 7) << 4));
                float4 v = *(const float4*)(Dp + off);
                acc[i][0] = v.x; acc[i][1] = v.y; acc[i][2] = v.z; acc[i][3] = v.w;
            }

            float logits[8];
            #pragma unroll
            for (int i = 0; i < 8; ++i) logits[i] = 0.f;
            float a0 = 0.f, a1 = 0.f, a2 = 0.f, a3 = 0.f;

            #pragma unroll
            for (int itr = 0; itr < 3; ++itr) {
                float r[8];
                #pragma unroll
                for (int i = 0; i < 8; ++i) {
                    float mm = logits[i];
                    mm = fmaxf(mm, __shfl_xor_sync(0xffffffffu, mm, 4));
                    mm = fmaxf(mm, __shfl_xor_sync(0xffffffffu, mm, 8));
                    mm = fmaxf(mm, __shfl_xor_sync(0xffffffffu, mm, 16));
                    float e = expf(logits[i] - mm);
                    float ss = e;
                    ss += __shfl_xor_sync(0xffffffffu, ss, 4);
                    ss += __shfl_xor_sync(0xffffffffu, ss, 8);
                    ss += __shfl_xor_sync(0xffffffffu, ss, 16);
                    r[i] = e / ss;
                }
                float p0 = bs.x, p1 = bs.y, p2 = bs.z, p3 = bs.w;
                #pragma unroll
                for (int i = 0; i < 8; ++i) {
                    p0 = fmaf(r[i], acc[i][0], p0);
                    p1 = fmaf(r[i], acc[i][1], p1);
                    p2 = fmaf(r[i], acc[i][2], p2);
                    p3 = fmaf(r[i], acc[i][3], p3);
                }
                float sq = p0 * p0 + p1 * p1 + p2 * p2 + p3 * p3;
                sq += __shfl_xor_sync(0xffffffffu, sq, 1);
                sq += __shfl_xor_sync(0xffffffffu, sq, 2);
                float scale = sq / ((1.0f + sq) * sqrtf(sq + 1e-9f));
                a0 = p0 * scale; a1 = p1 * scale; a2 = p2 * scale; a3 = p3 * scale;

                if (itr < 2) {
                    #pragma unroll
                    for (int i = 0; i < 8; ++i) {
                        float dd = acc[i][0] * a0 + acc[i][1] * a1
                                 + acc[i][2] * a2 + acc[i][3] * a3;
                        dd += __shfl_xor_sync(0xffffffffu, dd, 1);
                        dd += __shfl_xor_sync(0xffffffffu, dd, 2);
                        logits[i] += dd;
                    }
                }
            }

            const int P   = (base + it) * 16 + p;
            const int b   = P / 3136;
            const int rem = P - b * 3136;
            const int hh  = rem / 56, ww = rem - (rem / 56) * 56;
            const int h   = hpar + 2 * hh;
            const int w   = wpar + 2 * ww;
            ((float4*)out)[(size_t)((b * HP + h) * WP + w) * 32 + lane]
                = make_float4(a0, a1, a2, a3);
        }
        __syncthreads();   // routing reads done before acur is re-gathered (it+2)
    }
}

extern "C" void kernel_launch(void* const* d_in, const int* in_sizes, int n_in,
                              void* d_out, int out_size) {
    const float* x = nullptr;
    const float* W = nullptr;
    const float* bias = nullptr;
    for (int i = 0; i < n_in; ++i) {
        if (in_sizes[i] == XN)                    x    = (const float*)d_in[i];
        else if (in_sizes[i] == 4 * 4 * 128 * 32) W    = (const float*)d_in[i];
        else if (in_sizes[i] == 128)              bias = (const float*)d_in[i];
    }
    float* out = (float*)d_out;

    cudaFuncSetAttribute(deconv_caps_pers_kernel,
                         cudaFuncAttributeMaxDynamicSharedMemorySize, SMEM_TOTAL);

    prep_B_kernel<<<(4 * 2 * 128 * 128 + 255) / 256, 256>>>(W);
    prep_x_kernel<<<(XN + 255) / 256, 256>>>(x);

    dim3 grid(NBLK, 4);
    deconv_caps_pers_kernel<<<grid, 256, SMEM_TOTAL>>>(bias, out);
}

// round 6
// speedup vs baseline: 1.2290x; 1.0547x over previous
#include <cuda_runtime.h>
#include <cuda_bf16.h>
#include <cstdint>

// DeconvCapsuleLayer, round 6: round-5 skeleton (persistent blocks, cp.async
// pipelined gather, bf16 3-term-split mma.sync) with 16 warps x (32x32) warp
// tiles to eliminate register spilling (round 4/5 hit the 255-reg cap -> LDL/STL
// spill traffic throttled the tensor pipe to ~20%).
//
// Reference quirk reproduced: route i of output batch b uses input
// (bb, cin) = ((8b+i)&3, (8b+i)>>2).

namespace {
constexpr int HIN = 56, WIN = 56, CIN = 8, AIN = 32;
constexpr int HP = 112, WP = 112;
constexpr int XN = 4 * 56 * 56 * 8 * 32;     // elements in x
// SMEM map: B 64KB (hi 32K + lo 32K) | Abuf0 64KB (hi+lo) | Abuf1 64KB
constexpr int SM_B  = 0;
constexpr int SM_A0 = 65536;
constexpr int SM_A1 = 131072;
constexpr int SMEM_TOTAL = 196608;
constexpr int NBLK = 37;                     // blocks per class (37*4 = 148)
}

// Pre-split, pre-swizzled B: [cls(4)][split(2)][n(128)][k(128)] bf16.
__device__ __nv_bfloat16 g_B[4 * 2 * 128 * 128];
// Pre-split x: [split(2)][bb][ii][jj][cin][ain] bf16
__device__ __nv_bfloat16 g_xs[2 * XN];

__global__ void prep_B_kernel(const float* __restrict__ W) {
    int idx = blockIdx.x * blockDim.x + threadIdx.x;
    if (idx >= 4 * 2 * 128 * 128) return;
    int k   = idx & 127;
    int n   = (idx >> 7) & 127;
    int sp  = (idx >> 14) & 1;
    int cls = idx >> 15;
    int t = k >> 5, ain = k & 31;
    int hpar = cls >> 1, wpar = cls & 1;
    int p = (1 - hpar) + 2 * (t >> 1);
    int q = (1 - wpar) + 2 * (t & 1);
    float wv = W[((p * 4 + q) * 128 + n) * AIN + ain];
    __nv_bfloat16 hi = __float2bfloat16(wv);
    __nv_bfloat16 val = (sp == 0) ? hi
                      : __float2bfloat16(wv - __bfloat162float(hi));
    uint32_t off = (uint32_t)(n * 256) + (((uint32_t)(k * 2)) ^ ((uint32_t)(n & 7) << 4));
    *(__nv_bfloat16*)((char*)g_B + (((size_t)(cls * 2 + sp)) << 15) + off) = val;
}

__global__ void prep_x_kernel(const float* __restrict__ x) {
    int idx = blockIdx.x * blockDim.x + threadIdx.x;
    if (idx >= XN) return;
    float v = x[idx];
    __nv_bfloat16 hi = __float2bfloat16(v);
    g_xs[idx]      = hi;
    g_xs[XN + idx] = __float2bfloat16(v - __bfloat162float(hi));
}

// ---------------- PTX helpers ----------------
__device__ __forceinline__ void cpa16(uint32_t dst, const void* src, uint32_t srcsize) {
    asm volatile("cp.async.cg.shared.global [%0], [%1], 16, %2;"
                 :: "r"(dst), "l"(src), "r"(srcsize) : "memory");
}
__device__ __forceinline__ void cpa_commit() {
    asm volatile("cp.async.commit_group;" ::: "memory");
}
__device__ __forceinline__ void ldm_x4(uint32_t* r, uint32_t addr) {
    asm volatile("ldmatrix.sync.aligned.m8n8.x4.shared.b16 {%0,%1,%2,%3}, [%4];"
                 : "=r"(r[0]), "=r"(r[1]), "=r"(r[2]), "=r"(r[3]) : "r"(addr));
}
__device__ __forceinline__ void mma_bf16(float* d, const uint32_t* a, const uint32_t* b) {
    asm volatile("mma.sync.aligned.m16n8k16.row.col.f32.bf16.bf16.f32 "
                 "{%0,%1,%2,%3}, {%4,%5,%6,%7}, {%8,%9}, {%0,%1,%2,%3};"
                 : "+f"(d[0]), "+f"(d[1]), "+f"(d[2]), "+f"(d[3])
                 : "r"(a[0]), "r"(a[1]), "r"(a[2]), "r"(a[3]), "r"(b[0]), "r"(b[1]));
}

__global__ void __launch_bounds__(512, 1)
deconv_caps_pers_kernel(const float* __restrict__ bias,
                        float* __restrict__ out)
{
    extern __shared__ char smem[];
    const uint32_t sbase = (uint32_t)__cvta_generic_to_shared(smem);
    const int tid  = threadIdx.x;
    const int lane = tid & 31;
    const int wid  = tid >> 5;
    const int cls  = blockIdx.y;
    const int blk  = blockIdx.x;
    const int hpar = cls >> 1, wpar = cls & 1;

    // tile range: 784 tiles over 37 blocks -> first 7 blocks get 22, rest 21
    const int base = blk * 21 + (blk < 7 ? blk : 7);
    const int cnt  = 21 + (blk < 7 ? 1 : 0);

    // ---- issue B copy (pre-swizzled, 64KB) via cp.async : group 0
    {
        const char* Bsrc = (const char*)g_B + ((size_t)cls << 16);
        #pragma unroll
        for (int i = 0; i < 8; ++i) {
            uint32_t o = (uint32_t)(tid + 512 * i) * 16;
            cpa16(sbase + SM_B + o, Bsrc + o, 16);
        }
        cpa_commit();
    }

    // ---- per-thread gather constants: row m = tid>>2, tap = tid&3
    const int m = tid >> 2, mytap = tid & 3;
    const int mypix = m >> 3, route = m & 7;
    const uint32_t rx_m = (uint32_t)(m & 7) << 4;

    // gather lambda (cp.async only; one tap per thread)
    auto gather = [&](int T, uint32_t abuf) {
        const int P   = T * 16 + mypix;
        const int b   = P / 3136;
        const int rem = P - b * 3136;
        const int hh  = rem / 56, ww = rem - (rem / 56) * 56;
        const int h   = hpar + 2 * hh;
        const int w   = wpar + 2 * ww;
        const int ih  = (h + 1) >> 1, jw = (w + 1) >> 1;
        const int nn  = b * 8 + route;         // reference reshape quirk
        const int bb  = nn & 3, cin = nn >> 2;
        const int ii = ih - (mytap >> 1);
        const int jj = jw - (mytap & 1);
        const bool valid = ((unsigned)ii < (unsigned)HIN) && ((unsigned)jj < (unsigned)WIN);
        const int iic = valid ? ii : 0, jjc = valid ? jj : 0;
        const uint32_t ssz = valid ? 16u : 0u;
        const char* shi = (const char*)(g_xs
            + (size_t)(((bb * HIN + iic) * WIN + jjc) * CIN + cin) * AIN);
        #pragma unroll
        for (int c = 0; c < 4; ++c) {
            const uint32_t cb  = (uint32_t)(mytap * 4 + c);
            const uint32_t dof = (uint32_t)m * 256 + ((cb << 4) ^ rx_m);
            cpa16(abuf + dof,         shi + c * 16,                  ssz);
            cpa16(abuf + 32768 + dof, shi + (size_t)XN * 2 + c * 16, ssz);
        }
        cpa_commit();
    };

    // ---- prologue: gather tile 0 : group 1
    gather(base, sbase + SM_A0);

    // ---- mainloop constants (warp tile: rows mb..mb+31, cols nbase..nbase+31)
    const int mb    = (wid & 3) * 32;
    const int nbase = (wid >> 2) * 32;
    const int ar = lane & 15;
    const uint32_t rowA0 = (uint32_t)((mb + ar) * 256);
    const uint32_t rowA1 = (uint32_t)((mb + 16 + ar) * 256);
    const uint32_t a_kl  = (uint32_t)((lane >> 4) << 4);
    const uint32_t rxA   = (uint32_t)(ar & 7) << 4;
    const int brr = (lane & 7) + ((lane >> 4) << 3);
    uint32_t rowB[2];
    #pragma unroll
    for (int nt = 0; nt < 2; ++nt)
        rowB[nt] = (uint32_t)((nbase + nt * 16 + brr) * 256);
    const uint32_t b_kl = (uint32_t)(((lane >> 3) & 1) << 4);
    const uint32_t rxB  = (uint32_t)(lane & 7) << 4;

    const float4 bs = __ldg((const float4*)bias + lane);

    #pragma unroll 1
    for (int it = 0; it < cnt; ++it) {
        const uint32_t acur = sbase + ((it & 1) ? SM_A1 : SM_A0);
        const bool pre = (it + 1 < cnt);
        if (pre) gather(base + it + 1, sbase + (((it + 1) & 1) ? SM_A1 : SM_A0));

        // wait for A(it) (and B on first iter); newest group (prefetch) may fly
        if (pre) asm volatile("cp.async.wait_group 1;" ::: "memory");
        else     asm volatile("cp.async.wait_group 0;" ::: "memory");
        __syncthreads();

        // ---- mainloop: 3 splits x 8 k-steps; warp tile 32x32
        float d[2][4][4];
        #pragma unroll
        for (int mi = 0; mi < 2; ++mi)
            #pragma unroll
            for (int nq = 0; nq < 4; ++nq)
                #pragma unroll
                for (int j = 0; j < 4; ++j) d[mi][nq][j] = 0.f;

        #pragma unroll
        for (int s = 0; s < 3; ++s) {
            const uint32_t Ab = acur + (s < 2 ? 0 : 32768);
            const uint32_t Bb = sbase + SM_B + (s == 1 ? 32768 : 0);
            #pragma unroll
            for (int k0 = 0; k0 < 128; k0 += 16) {
                const uint32_t ka = ((uint32_t)(k0 * 2) + a_kl) ^ rxA;
                const uint32_t kb = ((uint32_t)(k0 * 2) + b_kl) ^ rxB;
                uint32_t a[2][4];
                ldm_x4(a[0], Ab + rowA0 + ka);
                ldm_x4(a[1], Ab + rowA1 + ka);
                #pragma unroll
                for (int nt = 0; nt < 2; ++nt) {
                    uint32_t bf[4];
                    ldm_x4(bf, Bb + rowB[nt] + kb);
                    #pragma unroll
                    for (int mi = 0; mi < 2; ++mi) {
                        mma_bf16(d[mi][nt * 2 + 0], a[mi], bf + 0);
                        mma_bf16(d[mi][nt * 2 + 1], a[mi], bf + 2);
                    }
                }
            }
        }
        __syncthreads();   // all ldmatrix A reads done before D overlays acur

        // ---- stage D into acur (pitch 512B, swizzled)
        {
            const int g  = lane >> 2;
            const int c2 = (lane & 3) * 2;
            char* Dp = smem + (acur - sbase);
            #pragma unroll
            for (int mi = 0; mi < 2; ++mi) {
                #pragma unroll
                for (int nq = 0; nq < 4; ++nq) {
                    const int col = nbase + nq * 8 + c2;
                    const int r0  = mb + mi * 16 + g;
                    const uint32_t cb = (uint32_t)(col * 4);
                    uint32_t o0 = (uint32_t)(r0 * 512) + (cb ^ ((uint32_t)(r0 & 7) << 4));
                    uint32_t o1 = (uint32_t)((r0 + 8) * 512) + (cb ^ ((uint32_t)((r0 + 8) & 7) << 4));
                    *(float2*)(Dp + o0) = make_float2(d[mi][nq][0], d[mi][nq][1]);
                    *(float2*)(Dp + o1) = make_float2(d[mi][nq][2], d[mi][nq][3]);
                }
            }
        }
        __syncthreads();

        // ---- routing: one pixel per warp (p = wid); lane owns ca = 4*lane+{0..3}
        {
            const char* Dp = smem + (acur - sbase);
            const int p = wid;
            float acc[8][4];
            #pragma unroll
            for (int i = 0; i < 8; ++i) {
                const int row = p * 8 + i;
                uint32_t off = (uint32_t)(row * 512)
                             + (((uint32_t)(lane * 16)) ^ ((uint32_t)(row & 7) << 4));
                float4 v = *(const float4*)(Dp + off);
                acc[i][0] = v.x; acc[i][1] = v.y; acc[i][2] = v.z; acc[i][3] = v.w;
            }

            float logits[8];
            #pragma unroll
            for (int i = 0; i < 8; ++i) logits[i] = 0.f;
            float a0 = 0.f, a1 = 0.f, a2 = 0.f, a3 = 0.f;

            #pragma unroll
            for (int itr = 0; itr < 3; ++itr) {
                float r[8];
                #pragma unroll
                for (int i = 0; i < 8; ++i) {
                    float mm = logits[i];
                    mm = fmaxf(mm, __shfl_xor_sync(0xffffffffu, mm, 4));
                    mm = fmaxf(mm, __shfl_xor_sync(0xffffffffu, mm, 8));
                    mm = fmaxf(mm, __shfl_xor_sync(0xffffffffu, mm, 16));
                    float e = expf(logits[i] - mm);
                    float ss = e;
                    ss += __shfl_xor_sync(0xffffffffu, ss, 4);
                    ss += __shfl_xor_sync(0xffffffffu, ss, 8);
                    ss += __shfl_xor_sync(0xffffffffu, ss, 16);
                    r[i] = e / ss;
                }
                float p0 = bs.x, p1 = bs.y, p2 = bs.z, p3 = bs.w;
                #pragma unroll
                for (int i = 0; i < 8; ++i) {
                    p0 = fmaf(r[i], acc[i][0], p0);
                    p1 = fmaf(r[i], acc[i][1], p1);
                    p2 = fmaf(r[i], acc[i][2], p2);
                    p3 = fmaf(r[i], acc[i][3], p3);
                }
                float sq = p0 * p0 + p1 * p1 + p2 * p2 + p3 * p3;
                sq += __shfl_xor_sync(0xffffffffu, sq, 1);
                sq += __shfl_xor_sync(0xffffffffu, sq, 2);
                float scale = sq / ((1.0f + sq) * sqrtf(sq + 1e-9f));
                a0 = p0 * scale; a1 = p1 * scale; a2 = p2 * scale; a3 = p3 * scale;

                if (itr < 2) {
                    #pragma unroll
                    for (int i = 0; i < 8; ++i) {
                        float dd = acc[i][0] * a0 + acc[i][1] * a1
                                 + acc[i][2] * a2 + acc[i][3] * a3;
                        dd += __shfl_xor_sync(0xffffffffu, dd, 1);
                        dd += __shfl_xor_sync(0xffffffffu, dd, 2);
                        logits[i] += dd;
                    }
                }
            }

            const int P   = (base + it) * 16 + p;
            const int b   = P / 3136;
            const int rem = P - b * 3136;
            const int hh  = rem / 56, ww = rem - (rem / 56) * 56;
            const int h   = hpar + 2 * hh;
            const int w   = wpar + 2 * ww;
            ((float4*)out)[(size_t)((b * HP + h) * WP + w) * 32 + lane]
                = make_float4(a0, a1, a2, a3);
        }
        __syncthreads();   // routing reads done before acur is re-gathered (it+2)
    }
}

extern "C" void kernel_launch(void* const* d_in, const int* in_sizes, int n_in,
                              void* d_out, int out_size) {
    const float* x = nullptr;
    const float* W = nullptr;
    const float* bias = nullptr;
    for (int i = 0; i < n_in; ++i) {
        if (in_sizes[i] == XN)                    x    = (const float*)d_in[i];
        else if (in_sizes[i] == 4 * 4 * 128 * 32) W    = (const float*)d_in[i];
        else if (in_sizes[i] == 128)              bias = (const float*)d_in[i];
    }
    float* out = (float*)d_out;

    cudaFuncSetAttribute(deconv_caps_pers_kernel,
                         cudaFuncAttributeMaxDynamicSharedMemorySize, SMEM_TOTAL);

    prep_B_kernel<<<(4 * 2 * 128 * 128 + 255) / 256, 256>>>(W);
    prep_x_kernel<<<(XN + 255) / 256, 256>>>(x);

    dim3 grid(NBLK, 4);
    deconv_caps_pers_kernel<<<grid, 512, SMEM_TOTAL>>>(bias, out);
}

// round 7
// speedup vs baseline: 1.3375x; 1.0883x over previous
#include <cuda_runtime.h>
#include <cuda_bf16.h>
#include <cstdint>

// DeconvCapsuleLayer, round 7: M=64 tiles -> 96KB smem -> 2 blocks/SM so two
// independent phase chains (GEMM / routing / barriers) overlap per SM.
// bf16 3-term split mma.sync (hi*hi + hi*lo + lo*hi) ~ fp32 accuracy.
// Single prep kernel (2 launches per call -> ncu -s 5 hits the main kernel).
//
// Reference quirk reproduced: route i of output batch b uses input
// (bb, cin) = ((8b+i)&3, (8b+i)>>2).

namespace {
constexpr int HIN = 56, WIN = 56, CIN = 8, AIN = 32;
constexpr int HP = 112, WP = 112;
constexpr int XN = 4 * 56 * 56 * 8 * 32;     // elements in x
constexpr int BN = 4 * 2 * 128 * 128;        // elements in split B
// SMEM map: B 64KB (hi 32K + lo 32K) | A 32KB (hi 16K + lo 16K). D overlays A.
constexpr int SM_B = 0;
constexpr int SM_A = 65536;
constexpr int SMEM_TOTAL = 98304;
constexpr int NBLK = 74;                     // blocks per class (74*4 = 296)
}

// Pre-split, pre-swizzled B: [cls(4)][split(2)][n(128)][k(128)] bf16.
__device__ __nv_bfloat16 g_B[BN];
// Pre-split x: [split(2)][bb][ii][jj][cin][ain] bf16
__device__ __nv_bfloat16 g_xs[2 * XN];

__global__ void prep_kernel(const float* __restrict__ W,
                            const float* __restrict__ x) {
    int idx = blockIdx.x * blockDim.x + threadIdx.x;
    if (idx < BN) {
        int k   = idx & 127;
        int n   = (idx >> 7) & 127;
        int sp  = (idx >> 14) & 1;
        int cls = idx >> 15;
        int t = k >> 5, ain = k & 31;
        int hpar = cls >> 1, wpar = cls & 1;
        int p = (1 - hpar) + 2 * (t >> 1);
        int q = (1 - wpar) + 2 * (t & 1);
        float wv = W[((p * 4 + q) * 128 + n) * AIN + ain];
        __nv_bfloat16 hi = __float2bfloat16(wv);
        __nv_bfloat16 val = (sp == 0) ? hi
                          : __float2bfloat16(wv - __bfloat162float(hi));
        uint32_t off = (uint32_t)(n * 256)
                     + (((uint32_t)(k * 2)) ^ ((uint32_t)(n & 7) << 4));
        *(__nv_bfloat16*)((char*)g_B + (((size_t)(cls * 2 + sp)) << 15) + off) = val;
    }
    if (idx < XN) {
        float v = x[idx];
        __nv_bfloat16 hi = __float2bfloat16(v);
        g_xs[idx]      = hi;
        g_xs[XN + idx] = __float2bfloat16(v - __bfloat162float(hi));
    }
}

// ---------------- PTX helpers ----------------
__device__ __forceinline__ void cpa16(uint32_t dst, const void* src, uint32_t srcsize) {
    asm volatile("cp.async.cg.shared.global [%0], [%1], 16, %2;"
                 :: "r"(dst), "l"(src), "r"(srcsize) : "memory");
}
__device__ __forceinline__ void cpa_commit() {
    asm volatile("cp.async.commit_group;" ::: "memory");
}
__device__ __forceinline__ void ldm_x4(uint32_t* r, uint32_t addr) {
    asm volatile("ldmatrix.sync.aligned.m8n8.x4.shared.b16 {%0,%1,%2,%3}, [%4];"
                 : "=r"(r[0]), "=r"(r[1]), "=r"(r[2]), "=r"(r[3]) : "r"(addr));
}
__device__ __forceinline__ void mma_bf16(float* d, const uint32_t* a, const uint32_t* b) {
    asm volatile("mma.sync.aligned.m16n8k16.row.col.f32.bf16.bf16.f32 "
                 "{%0,%1,%2,%3}, {%4,%5,%6,%7}, {%8,%9}, {%0,%1,%2,%3};"
                 : "+f"(d[0]), "+f"(d[1]), "+f"(d[2]), "+f"(d[3])
                 : "r"(a[0]), "r"(a[1]), "r"(a[2]), "r"(a[3]), "r"(b[0]), "r"(b[1]));
}

__global__ void __launch_bounds__(256, 2)
deconv_caps_pers_kernel(const float* __restrict__ bias,
                        float* __restrict__ out)
{
    extern __shared__ char smem[];
    const uint32_t sbase = (uint32_t)__cvta_generic_to_shared(smem);
    const int tid  = threadIdx.x;
    const int lane = tid & 31;
    const int wid  = tid >> 5;
    const int cls  = blockIdx.y;
    const int blk  = blockIdx.x;
    const int hpar = cls >> 1, wpar = cls & 1;

    // tile range: 1568 tiles over 74 blocks -> first 14 get 22, rest 21
    const int base = blk * 21 + (blk < 14 ? blk : 14);
    const int cnt  = 21 + (blk < 14 ? 1 : 0);

    // ---- issue B copy (pre-swizzled, 64KB) via cp.async
    {
        const char* Bsrc = (const char*)g_B + ((size_t)cls << 16);
        #pragma unroll
        for (int i = 0; i < 16; ++i) {
            uint32_t o = (uint32_t)(tid + 256 * i) * 16;
            cpa16(sbase + SM_B + o, Bsrc + o, 16);
        }
        cpa_commit();
    }

    // ---- per-thread gather constants: row m = tid>>2 (0..63), tap = tid&3
    const int m = tid >> 2, mytap = tid & 3;
    const int mypix = m >> 3, route = m & 7;   // pixel 0..7 within tile
    const uint32_t rx_m = (uint32_t)(m & 7) << 4;

    auto gather = [&](int T) {
        const int P   = T * 8 + mypix;
        const int b   = P / 3136;
        const int rem = P - b * 3136;
        const int hh  = rem / 56, ww = rem - (rem / 56) * 56;
        const int h   = hpar + 2 * hh;
        const int w   = wpar + 2 * ww;
        const int ih  = (h + 1) >> 1, jw = (w + 1) >> 1;
        const int nn  = b * 8 + route;         // reference reshape quirk
        const int bb  = nn & 3, cin = nn >> 2;
        const int ii = ih - (mytap >> 1);
        const int jj = jw - (mytap & 1);
        const bool valid = ((unsigned)ii < (unsigned)HIN) && ((unsigned)jj < (unsigned)WIN);
        const int iic = valid ? ii : 0, jjc = valid ? jj : 0;
        const uint32_t ssz = valid ? 16u : 0u;
        const char* shi = (const char*)(g_xs
            + (size_t)(((bb * HIN + iic) * WIN + jjc) * CIN + cin) * AIN);
        #pragma unroll
        for (int c = 0; c < 4; ++c) {
            const uint32_t cb  = (uint32_t)(mytap * 4 + c);
            const uint32_t dof = (uint32_t)m * 256 + ((cb << 4) ^ rx_m);
            cpa16(sbase + SM_A + dof,         shi + c * 16,                  ssz);
            cpa16(sbase + SM_A + 16384 + dof, shi + (size_t)XN * 2 + c * 16, ssz);
        }
        cpa_commit();
    };

    // ---- mainloop constants: warp tile rows mb..mb+31 (of 64), cols nbase..+31
    const int mb    = (wid & 1) * 32;
    const int nbase = (wid >> 1) * 32;
    const int ar = lane & 15;
    const uint32_t rowA0 = (uint32_t)((mb + ar) * 256);
    const uint32_t rowA1 = (uint32_t)((mb + 16 + ar) * 256);
    const uint32_t a_kl  = (uint32_t)((lane >> 4) << 4);
    const uint32_t rxA   = (uint32_t)(ar & 7) << 4;
    const int brr = (lane & 7) + ((lane >> 4) << 3);
    uint32_t rowB[2];
    #pragma unroll
    for (int nt = 0; nt < 2; ++nt)
        rowB[nt] = (uint32_t)((nbase + nt * 16 + brr) * 256);
    const uint32_t b_kl = (uint32_t)(((lane >> 3) & 1) << 4);
    const uint32_t rxB  = (uint32_t)(lane & 7) << 4;

    const float4 bs = __ldg((const float4*)bias + lane);

    // prologue gather of tile 0
    gather(base);

    #pragma unroll 1
    for (int it = 0; it < cnt; ++it) {
        asm volatile("cp.async.wait_group 0;" ::: "memory");
        __syncthreads();

        // ---- mainloop: 3 splits x 8 k-steps; warp tile 32x32
        float d[2][4][4];
        #pragma unroll
        for (int mi = 0; mi < 2; ++mi)
            #pragma unroll
            for (int nq = 0; nq < 4; ++nq)
                #pragma unroll
                for (int j = 0; j < 4; ++j) d[mi][nq][j] = 0.f;

        #pragma unroll
        for (int s = 0; s < 3; ++s) {
            const uint32_t Ab = sbase + SM_A + (s < 2 ? 0 : 16384);
            const uint32_t Bb = sbase + SM_B + (s == 1 ? 32768 : 0);
            #pragma unroll
            for (int k0 = 0; k0 < 128; k0 += 16) {
                const uint32_t ka = ((uint32_t)(k0 * 2) + a_kl) ^ rxA;
                const uint32_t kb = ((uint32_t)(k0 * 2) + b_kl) ^ rxB;
                uint32_t a[2][4];
                ldm_x4(a[0], Ab + rowA0 + ka);
                ldm_x4(a[1], Ab + rowA1 + ka);
                #pragma unroll
                for (int nt = 0; nt < 2; ++nt) {
                    uint32_t bf[4];
                    ldm_x4(bf, Bb + rowB[nt] + kb);
                    #pragma unroll
                    for (int mi = 0; mi < 2; ++mi) {
                        mma_bf16(d[mi][nt * 2 + 0], a[mi], bf + 0);
                        mma_bf16(d[mi][nt * 2 + 1], a[mi], bf + 2);
                    }
                }
            }
        }
        __syncthreads();   // all ldmatrix A reads done before D overlays A

        // ---- stage D into A region (pitch 512B, swizzled): 64 rows x 512B
        {
            const int g  = lane >> 2;
            const int c2 = (lane & 3) * 2;
            char* Dp = smem + SM_A;
            #pragma unroll
            for (int mi = 0; mi < 2; ++mi) {
                #pragma unroll
                for (int nq = 0; nq < 4; ++nq) {
                    const int col = nbase + nq * 8 + c2;
                    const int r0  = mb + mi * 16 + g;
                    const uint32_t cb = (uint32_t)(col * 4);
                    uint32_t o0 = (uint32_t)(r0 * 512) + (cb ^ ((uint32_t)(r0 & 7) << 4));
                    uint32_t o1 = (uint32_t)((r0 + 8) * 512) + (cb ^ ((uint32_t)((r0 + 8) & 7) << 4));
                    *(float2*)(Dp + o0) = make_float2(d[mi][nq][0], d[mi][nq][1]);
                    *(float2*)(Dp + o1) = make_float2(d[mi][nq][2], d[mi][nq][3]);
                }
            }
        }
        __syncthreads();

        // ---- routing: one pixel per warp (p = wid, 0..7)
        {
            const char* Dp = smem + SM_A;
            const int p = wid;
            float acc[8][4];
            #pragma unroll
            for (int i = 0; i < 8; ++i) {
                const int row = p * 8 + i;
                uint32_t off = (uint32_t)(row * 512)
                             + (((uint32_t)(lane * 16)) ^ ((uint32_t)(row & 7) << 4));
                float4 v = *(const float4*)(Dp + off);
                acc[i][0] = v.x; acc[i][1] = v.y; acc[i][2] = v.z; acc[i][3] = v.w;
            }

            float logits[8];
            #pragma unroll
            for (int i = 0; i < 8; ++i) logits[i] = 0.f;
            float a0 = 0.f, a1 = 0.f, a2 = 0.f, a3 = 0.f;

            #pragma unroll
            for (int itr = 0; itr < 3; ++itr) {
                float r[8];
                #pragma unroll
                for (int i = 0; i < 8; ++i) {
                    float mm = logits[i];
                    mm = fmaxf(mm, __shfl_xor_sync(0xffffffffu, mm, 4));
                    mm = fmaxf(mm, __shfl_xor_sync(0xffffffffu, mm, 8));
                    mm = fmaxf(mm, __shfl_xor_sync(0xffffffffu, mm, 16));
                    float e = expf(logits[i] - mm);
                    float ss = e;
                    ss += __shfl_xor_sync(0xffffffffu, ss, 4);
                    ss += __shfl_xor_sync(0xffffffffu, ss, 8);
                    ss += __shfl_xor_sync(0xffffffffu, ss, 16);
                    r[i] = e / ss;
                }
                float p0 = bs.x, p1 = bs.y, p2 = bs.z, p3 = bs.w;
                #pragma unroll
                for (int i = 0; i < 8; ++i) {
                    p0 = fmaf(r[i], acc[i][0], p0);
                    p1 = fmaf(r[i], acc[i][1], p1);
                    p2 = fmaf(r[i], acc[i][2], p2);
                    p3 = fmaf(r[i], acc[i][3], p3);
                }
                float sq = p0 * p0 + p1 * p1 + p2 * p2 + p3 * p3;
                sq += __shfl_xor_sync(0xffffffffu, sq, 1);
                sq += __shfl_xor_sync(0xffffffffu, sq, 2);
                float scale = sq / ((1.0f + sq) * sqrtf(sq + 1e-9f));
                a0 = p0 * scale; a1 = p1 * scale; a2 = p2 * scale; a3 = p3 * scale;

                if (itr < 2) {
                    #pragma unroll
                    for (int i = 0; i < 8; ++i) {
                        float dd = acc[i][0] * a0 + acc[i][1] * a1
                                 + acc[i][2] * a2 + acc[i][3] * a3;
                        dd += __shfl_xor_sync(0xffffffffu, dd, 1);
                        dd += __shfl_xor_sync(0xffffffffu, dd, 2);
                        logits[i] += dd;
                    }
                }
            }

            const int P   = (base + it) * 8 + p;
            const int b   = P / 3136;
            const int rem = P - b * 3136;
            const int hh  = rem / 56, ww = rem - (rem / 56) * 56;
            const int h   = hpar + 2 * hh;
            const int w   = wpar + 2 * ww;
            ((float4*)out)[(size_t)((b * HP + h) * WP + w) * 32 + lane]
                = make_float4(a0, a1, a2, a3);
        }
        __syncthreads();   // routing reads done before A is re-gathered

        if (it + 1 < cnt) gather(base + it + 1);
    }
}

extern "C" void kernel_launch(void* const* d_in, const int* in_sizes, int n_in,
                              void* d_out, int out_size) {
    const float* x = nullptr;
    const float* W = nullptr;
    const float* bias = nullptr;
    for (int i = 0; i < n_in; ++i) {
        if (in_sizes[i] == XN)                    x    = (const float*)d_in[i];
        else if (in_sizes[i] == 4 * 4 * 128 * 32) W    = (const float*)d_in[i];
        else if (in_sizes[i] == 128)              bias = (const float*)d_in[i];
    }
    float* out = (float*)d_out;

    cudaFuncSetAttribute(deconv_caps_pers_kernel,
                         cudaFuncAttributeMaxDynamicSharedMemorySize, SMEM_TOTAL);

    prep_kernel<<<(XN + 255) / 256, 256>>>(W, x);

    dim3 grid(NBLK, 4);
    deconv_caps_pers_kernel<<<grid, 256, SMEM_TOTAL>>>(bias, out);
}

// round 8
// speedup vs baseline: 1.6705x; 1.2490x over previous
#include <cuda_runtime.h>
#include <cuda_bf16.h>
#include <cstdint>

// DeconvCapsuleLayer, round 8: round-7 structure (M=64 tiles, 96KB smem,
// 2 blocks/SM, bf16 3-term split mma.sync) + slimmed routing:
//   - iteration-0 softmax == 0.125 exactly (logits start at 0) -> skipped
//   - no max-subtraction in softmax (|logits| <~ 8, exp safe)
//   - __expf / __fdividef (MUFU) instead of libm
// Routing shuffle count per warp-tile: ~200 -> 86.
//
// Reference quirk reproduced: route i of output batch b uses input
// (bb, cin) = ((8b+i)&3, (8b+i)>>2).

namespace {
constexpr int HIN = 56, WIN = 56, CIN = 8, AIN = 32;
constexpr int HP = 112, WP = 112;
constexpr int XN = 4 * 56 * 56 * 8 * 32;     // elements in x
constexpr int BN = 4 * 2 * 128 * 128;        // elements in split B
// SMEM map: B 64KB (hi 32K + lo 32K) | A 32KB (hi 16K + lo 16K). D overlays A.
constexpr int SM_B = 0;
constexpr int SM_A = 65536;
constexpr int SMEM_TOTAL = 98304;
constexpr int NBLK = 74;                     // blocks per class (74*4 = 296)
}

// Pre-split, pre-swizzled B: [cls(4)][split(2)][n(128)][k(128)] bf16.
__device__ __nv_bfloat16 g_B[BN];
// Pre-split x: [split(2)][bb][ii][jj][cin][ain] bf16
__device__ __nv_bfloat16 g_xs[2 * XN];

__global__ void prep_kernel(const float* __restrict__ W,
                            const float* __restrict__ x) {
    int idx = blockIdx.x * blockDim.x + threadIdx.x;
    if (idx < BN) {
        int k   = idx & 127;
        int n   = (idx >> 7) & 127;
        int sp  = (idx >> 14) & 1;
        int cls = idx >> 15;
        int t = k >> 5, ain = k & 31;
        int hpar = cls >> 1, wpar = cls & 1;
        int p = (1 - hpar) + 2 * (t >> 1);
        int q = (1 - wpar) + 2 * (t & 1);
        float wv = W[((p * 4 + q) * 128 + n) * AIN + ain];
        __nv_bfloat16 hi = __float2bfloat16(wv);
        __nv_bfloat16 val = (sp == 0) ? hi
                          : __float2bfloat16(wv - __bfloat162float(hi));
        uint32_t off = (uint32_t)(n * 256)
                     + (((uint32_t)(k * 2)) ^ ((uint32_t)(n & 7) << 4));
        *(__nv_bfloat16*)((char*)g_B + (((size_t)(cls * 2 + sp)) << 15) + off) = val;
    }
    if (idx < XN) {
        float v = x[idx];
        __nv_bfloat16 hi = __float2bfloat16(v);
        g_xs[idx]      = hi;
        g_xs[XN + idx] = __float2bfloat16(v - __bfloat162float(hi));
    }
}

// ---------------- PTX helpers ----------------
__device__ __forceinline__ void cpa16(uint32_t dst, const void* src, uint32_t srcsize) {
    asm volatile("cp.async.cg.shared.global [%0], [%1], 16, %2;"
                 :: "r"(dst), "l"(src), "r"(srcsize) : "memory");
}
__device__ __forceinline__ void cpa_commit() {
    asm volatile("cp.async.commit_group;" ::: "memory");
}
__device__ __forceinline__ void ldm_x4(uint32_t* r, uint32_t addr) {
    asm volatile("ldmatrix.sync.aligned.m8n8.x4.shared.b16 {%0,%1,%2,%3}, [%4];"
                 : "=r"(r[0]), "=r"(r[1]), "=r"(r[2]), "=r"(r[3]) : "r"(addr));
}
__device__ __forceinline__ void mma_bf16(float* d, const uint32_t* a, const uint32_t* b) {
    asm volatile("mma.sync.aligned.m16n8k16.row.col.f32.bf16.bf16.f32 "
                 "{%0,%1,%2,%3}, {%4,%5,%6,%7}, {%8,%9}, {%0,%1,%2,%3};"
                 : "+f"(d[0]), "+f"(d[1]), "+f"(d[2]), "+f"(d[3])
                 : "r"(a[0]), "r"(a[1]), "r"(a[2]), "r"(a[3]), "r"(b[0]), "r"(b[1]));
}

__global__ void __launch_bounds__(256, 2)
deconv_caps_pers_kernel(const float* __restrict__ bias,
                        float* __restrict__ out)
{
    extern __shared__ char smem[];
    const uint32_t sbase = (uint32_t)__cvta_generic_to_shared(smem);
    const int tid  = threadIdx.x;
    const int lane = tid & 31;
    const int wid  = tid >> 5;
    const int cls  = blockIdx.y;
    const int blk  = blockIdx.x;
    const int hpar = cls >> 1, wpar = cls & 1;

    // tile range: 1568 tiles over 74 blocks -> first 14 get 22, rest 21
    const int base = blk * 21 + (blk < 14 ? blk : 14);
    const int cnt  = 21 + (blk < 14 ? 1 : 0);

    // ---- issue B copy (pre-swizzled, 64KB) via cp.async
    {
        const char* Bsrc = (const char*)g_B + ((size_t)cls << 16);
        #pragma unroll
        for (int i = 0; i < 16; ++i) {
            uint32_t o = (uint32_t)(tid + 256 * i) * 16;
            cpa16(sbase + SM_B + o, Bsrc + o, 16);
        }
        cpa_commit();
    }

    // ---- per-thread gather constants: row m = tid>>2 (0..63), tap = tid&3
    const int m = tid >> 2, mytap = tid & 3;
    const int mypix = m >> 3, route = m & 7;   // pixel 0..7 within tile
    const uint32_t rx_m = (uint32_t)(m & 7) << 4;

    auto gather = [&](int T) {
        const int P   = T * 8 + mypix;
        const int b   = P / 3136;
        const int rem = P - b * 3136;
        const int hh  = rem / 56, ww = rem - (rem / 56) * 56;
        const int h   = hpar + 2 * hh;
        const int w   = wpar + 2 * ww;
        const int ih  = (h + 1) >> 1, jw = (w + 1) >> 1;
        const int nn  = b * 8 + route;         // reference reshape quirk
        const int bb  = nn & 3, cin = nn >> 2;
        const int ii = ih - (mytap >> 1);
        const int jj = jw - (mytap & 1);
        const bool valid = ((unsigned)ii < (unsigned)HIN) && ((unsigned)jj < (unsigned)WIN);
        const int iic = valid ? ii : 0, jjc = valid ? jj : 0;
        const uint32_t ssz = valid ? 16u : 0u;
        const char* shi = (const char*)(g_xs
            + (size_t)(((bb * HIN + iic) * WIN + jjc) * CIN + cin) * AIN);
        #pragma unroll
        for (int c = 0; c < 4; ++c) {
            const uint32_t cb  = (uint32_t)(mytap * 4 + c);
            const uint32_t dof = (uint32_t)m * 256 + ((cb << 4) ^ rx_m);
            cpa16(sbase + SM_A + dof,         shi + c * 16,                  ssz);
            cpa16(sbase + SM_A + 16384 + dof, shi + (size_t)XN * 2 + c * 16, ssz);
        }
        cpa_commit();
    };

    // ---- mainloop constants: warp tile rows mb..mb+31 (of 64), cols nbase..+31
    const int mb    = (wid & 1) * 32;
    const int nbase = (wid >> 1) * 32;
    const int ar = lane & 15;
    const uint32_t rowA0 = (uint32_t)((mb + ar) * 256);
    const uint32_t rowA1 = (uint32_t)((mb + 16 + ar) * 256);
    const uint32_t a_kl  = (uint32_t)((lane >> 4) << 4);
    const uint32_t rxA   = (uint32_t)(ar & 7) << 4;
    const int brr = (lane & 7) + ((lane >> 4) << 3);
    uint32_t rowB[2];
    #pragma unroll
    for (int nt = 0; nt < 2; ++nt)
        rowB[nt] = (uint32_t)((nbase + nt * 16 + brr) * 256);
    const uint32_t b_kl = (uint32_t)(((lane >> 3) & 1) << 4);
    const uint32_t rxB  = (uint32_t)(lane & 7) << 4;

    const float4 bs = __ldg((const float4*)bias + lane);

    // prologue gather of tile 0
    gather(base);

    #pragma unroll 1
    for (int it = 0; it < cnt; ++it) {
        asm volatile("cp.async.wait_group 0;" ::: "memory");
        __syncthreads();

        // ---- mainloop: 3 splits x 8 k-steps; warp tile 32x32
        float d[2][4][4];
        #pragma unroll
        for (int mi = 0; mi < 2; ++mi)
            #pragma unroll
            for (int nq = 0; nq < 4; ++nq)
                #pragma unroll
                for (int j = 0; j < 4; ++j) d[mi][nq][j] = 0.f;

        #pragma unroll
        for (int s = 0; s < 3; ++s) {
            const uint32_t Ab = sbase + SM_A + (s < 2 ? 0 : 16384);
            const uint32_t Bb = sbase + SM_B + (s == 1 ? 32768 : 0);
            #pragma unroll
            for (int k0 = 0; k0 < 128; k0 += 16) {
                const uint32_t ka = ((uint32_t)(k0 * 2) + a_kl) ^ rxA;
                const uint32_t kb = ((uint32_t)(k0 * 2) + b_kl) ^ rxB;
                uint32_t a[2][4];
                ldm_x4(a[0], Ab + rowA0 + ka);
                ldm_x4(a[1], Ab + rowA1 + ka);
                #pragma unroll
                for (int nt = 0; nt < 2; ++nt) {
                    uint32_t bf[4];
                    ldm_x4(bf, Bb + rowB[nt] + kb);
                    #pragma unroll
                    for (int mi = 0; mi < 2; ++mi) {
                        mma_bf16(d[mi][nt * 2 + 0], a[mi], bf + 0);
                        mma_bf16(d[mi][nt * 2 + 1], a[mi], bf + 2);
                    }
                }
            }
        }
        __syncthreads();   // all ldmatrix A reads done before D overlays A

        // ---- stage D into A region (pitch 512B, swizzled): 64 rows x 512B
        {
            const int g  = lane >> 2;
            const int c2 = (lane & 3) * 2;
            char* Dp = smem + SM_A;
            #pragma unroll
            for (int mi = 0; mi < 2; ++mi) {
                #pragma unroll
                for (int nq = 0; nq < 4; ++nq) {
                    const int col = nbase + nq * 8 + c2;
                    const int r0  = mb + mi * 16 + g;
                    const uint32_t cb = (uint32_t)(col * 4);
                    uint32_t o0 = (uint32_t)(r0 * 512) + (cb ^ ((uint32_t)(r0 & 7) << 4));
                    uint32_t o1 = (uint32_t)((r0 + 8) * 512) + (cb ^ ((uint32_t)((r0 + 8) & 7) << 4));
                    *(float2*)(Dp + o0) = make_float2(d[mi][nq][0], d[mi][nq][1]);
                    *(float2*)(Dp + o1) = make_float2(d[mi][nq][2], d[mi][nq][3]);
                }
            }
        }
        __syncthreads();

        // ---- routing: one pixel per warp (p = wid, 0..7)
        {
            const char* Dp = smem + SM_A;
            const int p = wid;
            float acc[8][4];
            #pragma unroll
            for (int i = 0; i < 8; ++i) {
                const int row = p * 8 + i;
                uint32_t off = (uint32_t)(row * 512)
                             + (((uint32_t)(lane * 16)) ^ ((uint32_t)(row & 7) << 4));
                float4 v = *(const float4*)(Dp + off);
                acc[i][0] = v.x; acc[i][1] = v.y; acc[i][2] = v.z; acc[i][3] = v.w;
            }

            float logits[8];
            float a0, a1, a2, a3;

            // ---- iteration 0: softmax(0) == 0.125 exactly
            {
                float p0 = bs.x, p1 = bs.y, p2 = bs.z, p3 = bs.w;
                float s0 = 0.f, s1 = 0.f, s2 = 0.f, s3 = 0.f;
                #pragma unroll
                for (int i = 0; i < 8; ++i) {
                    s0 += acc[i][0]; s1 += acc[i][1];
                    s2 += acc[i][2]; s3 += acc[i][3];
                }
                p0 = fmaf(0.125f, s0, p0); p1 = fmaf(0.125f, s1, p1);
                p2 = fmaf(0.125f, s2, p2); p3 = fmaf(0.125f, s3, p3);
                float sq = p0 * p0 + p1 * p1 + p2 * p2 + p3 * p3;
                sq += __shfl_xor_sync(0xffffffffu, sq, 1);
                sq += __shfl_xor_sync(0xffffffffu, sq, 2);
                float scale = sq / ((1.0f + sq) * sqrtf(sq + 1e-9f));
                a0 = p0 * scale; a1 = p1 * scale; a2 = p2 * scale; a3 = p3 * scale;
                #pragma unroll
                for (int i = 0; i < 8; ++i) {
                    float dd = acc[i][0] * a0 + acc[i][1] * a1
                             + acc[i][2] * a2 + acc[i][3] * a3;
                    dd += __shfl_xor_sync(0xffffffffu, dd, 1);
                    dd += __shfl_xor_sync(0xffffffffu, dd, 2);
                    logits[i] = dd;
                }
            }

            // ---- iterations 1,2: softmax without max-sub (|logits| small)
            #pragma unroll
            for (int itr = 1; itr < 3; ++itr) {
                float r[8];
                #pragma unroll
                for (int i = 0; i < 8; ++i) {
                    float e = __expf(logits[i]);
                    float ss = e;
                    ss += __shfl_xor_sync(0xffffffffu, ss, 4);
                    ss += __shfl_xor_sync(0xffffffffu, ss, 8);
                    ss += __shfl_xor_sync(0xffffffffu, ss, 16);
                    r[i] = __fdividef(e, ss);
                }
                float p0 = bs.x, p1 = bs.y, p2 = bs.z, p3 = bs.w;
                #pragma unroll
                for (int i = 0; i < 8; ++i) {
                    p0 = fmaf(r[i], acc[i][0], p0);
                    p1 = fmaf(r[i], acc[i][1], p1);
                    p2 = fmaf(r[i], acc[i][2], p2);
                    p3 = fmaf(r[i], acc[i][3], p3);
                }
                float sq = p0 * p0 + p1 * p1 + p2 * p2 + p3 * p3;
                sq += __shfl_xor_sync(0xffffffffu, sq, 1);
                sq += __shfl_xor_sync(0xffffffffu, sq, 2);
                float scale = sq / ((1.0f + sq) * sqrtf(sq + 1e-9f));
                a0 = p0 * scale; a1 = p1 * scale; a2 = p2 * scale; a3 = p3 * scale;

                if (itr == 1) {
                    #pragma unroll
                    for (int i = 0; i < 8; ++i) {
                        float dd = acc[i][0] * a0 + acc[i][1] * a1
                                 + acc[i][2] * a2 + acc[i][3] * a3;
                        dd += __shfl_xor_sync(0xffffffffu, dd, 1);
                        dd += __shfl_xor_sync(0xffffffffu, dd, 2);
                        logits[i] += dd;
                    }
                }
            }

            const int P   = (base + it) * 8 + p;
            const int b   = P / 3136;
            const int rem = P - b * 3136;
            const int hh  = rem / 56, ww = rem - (rem / 56) * 56;
            const int h   = hpar + 2 * hh;
            const int w   = wpar + 2 * ww;
            ((float4*)out)[(size_t)((b * HP + h) * WP + w) * 32 + lane]
                = make_float4(a0, a1, a2, a3);
        }
        __syncthreads();   // routing reads done before A is re-gathered

        if (it + 1 < cnt) gather(base + it + 1);
    }
}

extern "C" void kernel_launch(void* const* d_in, const int* in_sizes, int n_in,
                              void* d_out, int out_size) {
    const float* x = nullptr;
    const float* W = nullptr;
    const float* bias = nullptr;
    for (int i = 0; i < n_in; ++i) {
        if (in_sizes[i] == XN)                    x    = (const float*)d_in[i];
        else if (in_sizes[i] == 4 * 4 * 128 * 32) W    = (const float*)d_in[i];
        else if (in_sizes[i] == 128)              bias = (const float*)d_in[i];
    }
    float* out = (float*)d_out;

    cudaFuncSetAttribute(deconv_caps_pers_kernel,
                         cudaFuncAttributeMaxDynamicSharedMemorySize, SMEM_TOTAL);

    prep_kernel<<<(XN + 255) / 256, 256>>>(W, x);

    dim3 grid(NBLK, 4);
    deconv_caps_pers_kernel<<<grid, 256, SMEM_TOTAL>>>(bias, out);
}

// round 9
// speedup vs baseline: 2.0983x; 1.2561x over previous
#include <cuda_runtime.h>
#include <cuda_bf16.h>
#include <cstdint>

// DeconvCapsuleLayer, round 9: round-8 + (a) fragment reuse across the three
// bf16-split GEMMs (A_hi/B_hi frags loaded once per k-step; LDSM -33%) and
// (b) gather(t+1) hoisted before the routing math so cp.async latency hides
// under the shuffle chains.
//
// Reference quirk reproduced: route i of output batch b uses input
// (bb, cin) = ((8b+i)&3, (8b+i)>>2).

namespace {
constexpr int HIN = 56, WIN = 56, CIN = 8, AIN = 32;
constexpr int HP = 112, WP = 112;
constexpr int XN = 4 * 56 * 56 * 8 * 32;     // elements in x
constexpr int BN = 4 * 2 * 128 * 128;        // elements in split B
// SMEM map: B 64KB (hi 32K + lo 32K) | A 32KB (hi 16K + lo 16K). D overlays A.
constexpr int SM_B = 0;
constexpr int SM_A = 65536;
constexpr int SMEM_TOTAL = 98304;
constexpr int NBLK = 74;                     // blocks per class (74*4 = 296)
}

// Pre-split, pre-swizzled B: [cls(4)][split(2)][n(128)][k(128)] bf16.
__device__ __nv_bfloat16 g_B[BN];
// Pre-split x: [split(2)][bb][ii][jj][cin][ain] bf16
__device__ __nv_bfloat16 g_xs[2 * XN];

__global__ void prep_kernel(const float* __restrict__ W,
                            const float* __restrict__ x) {
    int idx = blockIdx.x * blockDim.x + threadIdx.x;
    if (idx < BN) {
        int k   = idx & 127;
        int n   = (idx >> 7) & 127;
        int sp  = (idx >> 14) & 1;
        int cls = idx >> 15;
        int t = k >> 5, ain = k & 31;
        int hpar = cls >> 1, wpar = cls & 1;
        int p = (1 - hpar) + 2 * (t >> 1);
        int q = (1 - wpar) + 2 * (t & 1);
        float wv = W[((p * 4 + q) * 128 + n) * AIN + ain];
        __nv_bfloat16 hi = __float2bfloat16(wv);
        __nv_bfloat16 val = (sp == 0) ? hi
                          : __float2bfloat16(wv - __bfloat162float(hi));
        uint32_t off = (uint32_t)(n * 256)
                     + (((uint32_t)(k * 2)) ^ ((uint32_t)(n & 7) << 4));
        *(__nv_bfloat16*)((char*)g_B + (((size_t)(cls * 2 + sp)) << 15) + off) = val;
    }
    if (idx < XN) {
        float v = x[idx];
        __nv_bfloat16 hi = __float2bfloat16(v);
        g_xs[idx]      = hi;
        g_xs[XN + idx] = __float2bfloat16(v - __bfloat162float(hi));
    }
}

// ---------------- PTX helpers ----------------
__device__ __forceinline__ void cpa16(uint32_t dst, const void* src, uint32_t srcsize) {
    asm volatile("cp.async.cg.shared.global [%0], [%1], 16, %2;"
                 :: "r"(dst), "l"(src), "r"(srcsize) : "memory");
}
__device__ __forceinline__ void cpa_commit() {
    asm volatile("cp.async.commit_group;" ::: "memory");
}
__device__ __forceinline__ void ldm_x4(uint32_t* r, uint32_t addr) {
    asm volatile("ldmatrix.sync.aligned.m8n8.x4.shared.b16 {%0,%1,%2,%3}, [%4];"
                 : "=r"(r[0]), "=r"(r[1]), "=r"(r[2]), "=r"(r[3]) : "r"(addr));
}
__device__ __forceinline__ void mma_bf16(float* d, const uint32_t* a, const uint32_t* b) {
    asm volatile("mma.sync.aligned.m16n8k16.row.col.f32.bf16.bf16.f32 "
                 "{%0,%1,%2,%3}, {%4,%5,%6,%7}, {%8,%9}, {%0,%1,%2,%3};"
                 : "+f"(d[0]), "+f"(d[1]), "+f"(d[2]), "+f"(d[3])
                 : "r"(a[0]), "r"(a[1]), "r"(a[2]), "r"(a[3]), "r"(b[0]), "r"(b[1]));
}

__global__ void __launch_bounds__(256, 2)
deconv_caps_pers_kernel(const float* __restrict__ bias,
                        float* __restrict__ out)
{
    extern __shared__ char smem[];
    const uint32_t sbase = (uint32_t)__cvta_generic_to_shared(smem);
    const int tid  = threadIdx.x;
    const int lane = tid & 31;
    const int wid  = tid >> 5;
    const int cls  = blockIdx.y;
    const int blk  = blockIdx.x;
    const int hpar = cls >> 1, wpar = cls & 1;

    // tile range: 1568 tiles over 74 blocks -> first 14 get 22, rest 21
    const int base = blk * 21 + (blk < 14 ? blk : 14);
    const int cnt  = 21 + (blk < 14 ? 1 : 0);

    // ---- issue B copy (pre-swizzled, 64KB) via cp.async
    {
        const char* Bsrc = (const char*)g_B + ((size_t)cls << 16);
        #pragma unroll
        for (int i = 0; i < 16; ++i) {
            uint32_t o = (uint32_t)(tid + 256 * i) * 16;
            cpa16(sbase + SM_B + o, Bsrc + o, 16);
        }
        cpa_commit();
    }

    // ---- per-thread gather constants: row m = tid>>2 (0..63), tap = tid&3
    const int m = tid >> 2, mytap = tid & 3;
    const int mypix = m >> 3, route = m & 7;   // pixel 0..7 within tile
    const uint32_t rx_m = (uint32_t)(m & 7) << 4;

    auto gather = [&](int T) {
        const int P   = T * 8 + mypix;
        const int b   = P / 3136;
        const int rem = P - b * 3136;
        const int hh  = rem / 56, ww = rem - (rem / 56) * 56;
        const int h   = hpar + 2 * hh;
        const int w   = wpar + 2 * ww;
        const int ih  = (h + 1) >> 1, jw = (w + 1) >> 1;
        const int nn  = b * 8 + route;         // reference reshape quirk
        const int bb  = nn & 3, cin = nn >> 2;
        const int ii = ih - (mytap >> 1);
        const int jj = jw - (mytap & 1);
        const bool valid = ((unsigned)ii < (unsigned)HIN) && ((unsigned)jj < (unsigned)WIN);
        const int iic = valid ? ii : 0, jjc = valid ? jj : 0;
        const uint32_t ssz = valid ? 16u : 0u;
        const char* shi = (const char*)(g_xs
            + (size_t)(((bb * HIN + iic) * WIN + jjc) * CIN + cin) * AIN);
        #pragma unroll
        for (int c = 0; c < 4; ++c) {
            const uint32_t cb  = (uint32_t)(mytap * 4 + c);
            const uint32_t dof = (uint32_t)m * 256 + ((cb << 4) ^ rx_m);
            cpa16(sbase + SM_A + dof,         shi + c * 16,                  ssz);
            cpa16(sbase + SM_A + 16384 + dof, shi + (size_t)XN * 2 + c * 16, ssz);
        }
        cpa_commit();
    };

    // ---- mainloop constants: warp tile rows mb..mb+31 (of 64), cols nbase..+31
    const int mb    = (wid & 1) * 32;
    const int nbase = (wid >> 1) * 32;
    const int ar = lane & 15;
    const uint32_t rowA0 = (uint32_t)((mb + ar) * 256);
    const uint32_t rowA1 = (uint32_t)((mb + 16 + ar) * 256);
    const uint32_t a_kl  = (uint32_t)((lane >> 4) << 4);
    const uint32_t rxA   = (uint32_t)(ar & 7) << 4;
    const int brr = (lane & 7) + ((lane >> 4) << 3);
    uint32_t rowB[2];
    #pragma unroll
    for (int nt = 0; nt < 2; ++nt)
        rowB[nt] = (uint32_t)((nbase + nt * 16 + brr) * 256);
    const uint32_t b_kl = (uint32_t)(((lane >> 3) & 1) << 4);
    const uint32_t rxB  = (uint32_t)(lane & 7) << 4;

    const float4 bs = __ldg((const float4*)bias + lane);

    // prologue gather of tile 0
    gather(base);

    #pragma unroll 1
    for (int it = 0; it < cnt; ++it) {
        asm volatile("cp.async.wait_group 0;" ::: "memory");
        __syncthreads();

        // ---- mainloop: 8 k-steps, frags reused across the 3 splits
        float d[2][4][4];
        #pragma unroll
        for (int mi = 0; mi < 2; ++mi)
            #pragma unroll
            for (int nq = 0; nq < 4; ++nq)
                #pragma unroll
                for (int j = 0; j < 4; ++j) d[mi][nq][j] = 0.f;

        {
            const uint32_t Ahi = sbase + SM_A;
            const uint32_t Alo = sbase + SM_A + 16384;
            const uint32_t Bhi = sbase + SM_B;
            const uint32_t Blo = sbase + SM_B + 32768;
            #pragma unroll
            for (int k0 = 0; k0 < 128; k0 += 16) {
                const uint32_t ka = ((uint32_t)(k0 * 2) + a_kl) ^ rxA;
                const uint32_t kb = ((uint32_t)(k0 * 2) + b_kl) ^ rxB;
                uint32_t ahi[2][4], alo[2][4], bhi[2][4], blo[4];
                ldm_x4(ahi[0], Ahi + rowA0 + ka);
                ldm_x4(ahi[1], Ahi + rowA1 + ka);
                #pragma unroll
                for (int nt = 0; nt < 2; ++nt) {
                    ldm_x4(bhi[nt], Bhi + rowB[nt] + kb);
                    #pragma unroll
                    for (int mi = 0; mi < 2; ++mi) {
                        mma_bf16(d[mi][nt * 2 + 0], ahi[mi], bhi[nt] + 0);
                        mma_bf16(d[mi][nt * 2 + 1], ahi[mi], bhi[nt] + 2);
                    }
                    ldm_x4(blo, Blo + rowB[nt] + kb);
                    #pragma unroll
                    for (int mi = 0; mi < 2; ++mi) {
                        mma_bf16(d[mi][nt * 2 + 0], ahi[mi], blo + 0);
                        mma_bf16(d[mi][nt * 2 + 1], ahi[mi], blo + 2);
                    }
                }
                ldm_x4(alo[0], Alo + rowA0 + ka);
                ldm_x4(alo[1], Alo + rowA1 + ka);
                #pragma unroll
                for (int nt = 0; nt < 2; ++nt) {
                    #pragma unroll
                    for (int mi = 0; mi < 2; ++mi) {
                        mma_bf16(d[mi][nt * 2 + 0], alo[mi], bhi[nt] + 0);
                        mma_bf16(d[mi][nt * 2 + 1], alo[mi], bhi[nt] + 2);
                    }
                }
            }
        }
        __syncthreads();   // all ldmatrix A reads done before D overlays A

        // ---- stage D into A region (pitch 512B, swizzled): 64 rows x 512B
        {
            const int g  = lane >> 2;
            const int c2 = (lane & 3) * 2;
            char* Dp = smem + SM_A;
            #pragma unroll
            for (int mi = 0; mi < 2; ++mi) {
                #pragma unroll
                for (int nq = 0; nq < 4; ++nq) {
                    const int col = nbase + nq * 8 + c2;
                    const int r0  = mb + mi * 16 + g;
                    const uint32_t cb = (uint32_t)(col * 4);
                    uint32_t o0 = (uint32_t)(r0 * 512) + (cb ^ ((uint32_t)(r0 & 7) << 4));
                    uint32_t o1 = (uint32_t)((r0 + 8) * 512) + (cb ^ ((uint32_t)((r0 + 8) & 7) << 4));
                    *(float2*)(Dp + o0) = make_float2(d[mi][nq][0], d[mi][nq][1]);
                    *(float2*)(Dp + o1) = make_float2(d[mi][nq][2], d[mi][nq][3]);
                }
            }
        }
        __syncthreads();

        // ---- load routing acc regs (one pixel per warp), then free A region
        float acc[8][4];
        {
            const char* Dp = smem + SM_A;
            #pragma unroll
            for (int i = 0; i < 8; ++i) {
                const int row = wid * 8 + i;
                uint32_t off = (uint32_t)(row * 512)
                             + (((uint32_t)(lane * 16)) ^ ((uint32_t)(row & 7) << 4));
                float4 v = *(const float4*)(Dp + off);
                acc[i][0] = v.x; acc[i][1] = v.y; acc[i][2] = v.z; acc[i][3] = v.w;
            }
        }
        __syncthreads();   // all D reads done before A region is re-gathered

        // ---- hoisted gather: cp.async latency hides under routing math
        if (it + 1 < cnt) gather(base + it + 1);

        // ---- routing math (registers + shuffles only)
        {
            float logits[8];
            float a0, a1, a2, a3;

            // iteration 0: softmax(0) == 0.125 exactly
            {
                float p0 = bs.x, p1 = bs.y, p2 = bs.z, p3 = bs.w;
                float s0 = 0.f, s1 = 0.f, s2 = 0.f, s3 = 0.f;
                #pragma unroll
                for (int i = 0; i < 8; ++i) {
                    s0 += acc[i][0]; s1 += acc[i][1];
                    s2 += acc[i][2]; s3 += acc[i][3];
                }
                p0 = fmaf(0.125f, s0, p0); p1 = fmaf(0.125f, s1, p1);
                p2 = fmaf(0.125f, s2, p2); p3 = fmaf(0.125f, s3, p3);
                float sq = p0 * p0 + p1 * p1 + p2 * p2 + p3 * p3;
                sq += __shfl_xor_sync(0xffffffffu, sq, 1);
                sq += __shfl_xor_sync(0xffffffffu, sq, 2);
                float scale = sq / ((1.0f + sq) * sqrtf(sq + 1e-9f));
                a0 = p0 * scale; a1 = p1 * scale; a2 = p2 * scale; a3 = p3 * scale;
                #pragma unroll
                for (int i = 0; i < 8; ++i) {
                    float dd = acc[i][0] * a0 + acc[i][1] * a1
                             + acc[i][2] * a2 + acc[i][3] * a3;
                    dd += __shfl_xor_sync(0xffffffffu, dd, 1);
                    dd += __shfl_xor_sync(0xffffffffu, dd, 2);
                    logits[i] = dd;
                }
            }

            // iterations 1,2: softmax without max-sub (|logits| small)
            #pragma unroll
            for (int itr = 1; itr < 3; ++itr) {
                float r[8];
                #pragma unroll
                for (int i = 0; i < 8; ++i) {
                    float e = __expf(logits[i]);
                    float ss = e;
                    ss += __shfl_xor_sync(0xffffffffu, ss, 4);
                    ss += __shfl_xor_sync(0xffffffffu, ss, 8);
                    ss += __shfl_xor_sync(0xffffffffu, ss, 16);
                    r[i] = __fdividef(e, ss);
                }
                float p0 = bs.x, p1 = bs.y, p2 = bs.z, p3 = bs.w;
                #pragma unroll
                for (int i = 0; i < 8; ++i) {
                    p0 = fmaf(r[i], acc[i][0], p0);
                    p1 = fmaf(r[i], acc[i][1], p1);
                    p2 = fmaf(r[i], acc[i][2], p2);
                    p3 = fmaf(r[i], acc[i][3], p3);
                }
                float sq = p0 * p0 + p1 * p1 + p2 * p2 + p3 * p3;
                sq += __shfl_xor_sync(0xffffffffu, sq, 1);
                sq += __shfl_xor_sync(0xffffffffu, sq, 2);
                float scale = sq / ((1.0f + sq) * sqrtf(sq + 1e-9f));
                a0 = p0 * scale; a1 = p1 * scale; a2 = p2 * scale; a3 = p3 * scale;

                if (itr == 1) {
                    #pragma unroll
                    for (int i = 0; i < 8; ++i) {
                        float dd = acc[i][0] * a0 + acc[i][1] * a1
                                 + acc[i][2] * a2 + acc[i][3] * a3;
                        dd += __shfl_xor_sync(0xffffffffu, dd, 1);
                        dd += __shfl_xor_sync(0xffffffffu, dd, 2);
                        logits[i] += dd;
                    }
                }
            }

            const int P   = (base + it) * 8 + wid;
            const int b   = P / 3136;
            const int rem = P - b * 3136;
            const int hh  = rem / 56, ww = rem - (rem / 56) * 56;
            const int h   = hpar + 2 * hh;
            const int w   = wpar + 2 * ww;
            ((float4*)out)[(size_t)((b * HP + h) * WP + w) * 32 + lane]
                = make_float4(a0, a1, a2, a3);
        }
    }
}

extern "C" void kernel_launch(void* const* d_in, const int* in_sizes, int n_in,
                              void* d_out, int out_size) {
    const float* x = nullptr;
    const float* W = nullptr;
    const float* bias = nullptr;
    for (int i = 0; i < n_in; ++i) {
        if (in_sizes[i] == XN)                    x    = (const float*)d_in[i];
        else if (in_sizes[i] == 4 * 4 * 128 * 32) W    = (const float*)d_in[i];
        else if (in_sizes[i] == 128)              bias = (const float*)d_in[i];
    }
    float* out = (float*)d_out;

    cudaFuncSetAttribute(deconv_caps_pers_kernel,
                         cudaFuncAttributeMaxDynamicSharedMemorySize, SMEM_TOTAL);

    prep_kernel<<<(XN + 255) / 256, 256>>>(W, x);

    dim3 grid(NBLK, 4);
    deconv_caps_pers_kernel<<<grid, 256, SMEM_TOTAL>>>(bias, out);
}

// round 10
// speedup vs baseline: 2.9718x; 1.4162x over previous
#include <cuda_runtime.h>
#include <cuda_fp16.h>
#include <cstdint>

// DeconvCapsuleLayer, round 10: 2-term fp16 split GEMM:
//   D = A_hi * (B_hi + B_lo),   fp16 operands (11 mantissa bits), fp32 accum.
// Dropped A_lo term ~2^-12 relative -> expected rel_err ~1e-4 (gate is 1e-3).
// vs round 9 (3-term bf16): MMA -33%, LDSM -25%, A smem/gather traffic -50%.
// Same skeleton: M=64 tiles, 96KB smem, 2 blocks/SM, persistent, cp.async
// gather hoisted under routing, slimmed register routing.
//
// Reference quirk reproduced: route i of output batch b uses input
// (bb, cin) = ((8b+i)&3, (8b+i)>>2).

namespace {
constexpr int HIN = 56, WIN = 56, CIN = 8, AIN = 32;
constexpr int HP = 112, WP = 112;
constexpr int XN = 4 * 56 * 56 * 8 * 32;     // elements in x
constexpr int BN = 4 * 2 * 128 * 128;        // elements in split B (hi+lo)
// SMEM map: B 64KB (hi 32K + lo 32K) | AD 32KB (A_hi uses first 16KB; D all 32KB)
constexpr int SM_B  = 0;
constexpr int SM_AD = 65536;
constexpr int SMEM_TOTAL = 98304;
constexpr int NBLK = 74;                     // blocks per class (74*4 = 296)
}

// Pre-split, pre-swizzled B: [cls(4)][split(2)][n(128)][k(128)] fp16.
__device__ __half g_B[BN];
// fp16 hi of x: [bb][ii][jj][cin][ain]
__device__ __half g_xh[XN];

__global__ void prep_kernel(const float* __restrict__ W,
                            const float* __restrict__ x) {
    int idx = blockIdx.x * blockDim.x + threadIdx.x;
    if (idx < BN) {
        int k   = idx & 127;
        int n   = (idx >> 7) & 127;
        int sp  = (idx >> 14) & 1;
        int cls = idx >> 15;
        int t = k >> 5, ain = k & 31;
        int hpar = cls >> 1, wpar = cls & 1;
        int p = (1 - hpar) + 2 * (t >> 1);
        int q = (1 - wpar) + 2 * (t & 1);
        float wv = W[((p * 4 + q) * 128 + n) * AIN + ain];
        __half hi = __float2half_rn(wv);
        __half val = (sp == 0) ? hi
                   : __float2half_rn(wv - __half2float(hi));
        uint32_t off = (uint32_t)(n * 256)
                     + (((uint32_t)(k * 2)) ^ ((uint32_t)(n & 7) << 4));
        *(__half*)((char*)g_B + (((size_t)(cls * 2 + sp)) << 15) + off) = val;
    }
    if (idx < XN) {
        g_xh[idx] = __float2half_rn(x[idx]);
    }
}

// ---------------- PTX helpers ----------------
__device__ __forceinline__ void cpa16(uint32_t dst, const void* src, uint32_t srcsize) {
    asm volatile("cp.async.cg.shared.global [%0], [%1], 16, %2;"
                 :: "r"(dst), "l"(src), "r"(srcsize) : "memory");
}
__device__ __forceinline__ void cpa_commit() {
    asm volatile("cp.async.commit_group;" ::: "memory");
}
__device__ __forceinline__ void ldm_x4(uint32_t* r, uint32_t addr) {
    asm volatile("ldmatrix.sync.aligned.m8n8.x4.shared.b16 {%0,%1,%2,%3}, [%4];"
                 : "=r"(r[0]), "=r"(r[1]), "=r"(r[2]), "=r"(r[3]) : "r"(addr));
}
__device__ __forceinline__ void mma_f16(float* d, const uint32_t* a, const uint32_t* b) {
    asm volatile("mma.sync.aligned.m16n8k16.row.col.f32.f16.f16.f32 "
                 "{%0,%1,%2,%3}, {%4,%5,%6,%7}, {%8,%9}, {%0,%1,%2,%3};"
                 : "+f"(d[0]), "+f"(d[1]), "+f"(d[2]), "+f"(d[3])
                 : "r"(a[0]), "r"(a[1]), "r"(a[2]), "r"(a[3]), "r"(b[0]), "r"(b[1]));
}

__global__ void __launch_bounds__(256, 2)
deconv_caps_pers_kernel(const float* __restrict__ bias,
                        float* __restrict__ out)
{
    extern __shared__ char smem[];
    const uint32_t sbase = (uint32_t)__cvta_generic_to_shared(smem);
    const int tid  = threadIdx.x;
    const int lane = tid & 31;
    const int wid  = tid >> 5;
    const int cls  = blockIdx.y;
    const int blk  = blockIdx.x;
    const int hpar = cls >> 1, wpar = cls & 1;

    // tile range: 1568 tiles over 74 blocks -> first 14 get 22, rest 21
    const int base = blk * 21 + (blk < 14 ? blk : 14);
    const int cnt  = 21 + (blk < 14 ? 1 : 0);

    // ---- issue B copy (pre-swizzled, 64KB) via cp.async
    {
        const char* Bsrc = (const char*)g_B + ((size_t)cls << 16);
        #pragma unroll
        for (int i = 0; i < 16; ++i) {
            uint32_t o = (uint32_t)(tid + 256 * i) * 16;
            cpa16(sbase + SM_B + o, Bsrc + o, 16);
        }
        cpa_commit();
    }

    // ---- per-thread gather constants: row m = tid>>2 (0..63), tap = tid&3
    const int m = tid >> 2, mytap = tid & 3;
    const int mypix = m >> 3, route = m & 7;   // pixel 0..7 within tile
    const uint32_t rx_m = (uint32_t)(m & 7) << 4;

    auto gather = [&](int T) {
        const int P   = T * 8 + mypix;
        const int b   = P / 3136;
        const int rem = P - b * 3136;
        const int hh  = rem / 56, ww = rem - (rem / 56) * 56;
        const int h   = hpar + 2 * hh;
        const int w   = wpar + 2 * ww;
        const int ih  = (h + 1) >> 1, jw = (w + 1) >> 1;
        const int nn  = b * 8 + route;         // reference reshape quirk
        const int bb  = nn & 3, cin = nn >> 2;
        const int ii = ih - (mytap >> 1);
        const int jj = jw - (mytap & 1);
        const bool valid = ((unsigned)ii < (unsigned)HIN) && ((unsigned)jj < (unsigned)WIN);
        const int iic = valid ? ii : 0, jjc = valid ? jj : 0;
        const uint32_t ssz = valid ? 16u : 0u;
        const char* shi = (const char*)(g_xh
            + (size_t)(((bb * HIN + iic) * WIN + jjc) * CIN + cin) * AIN);
        #pragma unroll
        for (int c = 0; c < 4; ++c) {
            const uint32_t cb  = (uint32_t)(mytap * 4 + c);
            const uint32_t dof = (uint32_t)m * 256 + ((cb << 4) ^ rx_m);
            cpa16(sbase + SM_AD + dof, shi + c * 16, ssz);
        }
        cpa_commit();
    };

    // ---- mainloop constants: warp tile rows mb..mb+31 (of 64), cols nbase..+31
    const int mb    = (wid & 1) * 32;
    const int nbase = (wid >> 1) * 32;
    const int ar = lane & 15;
    const uint32_t rowA0 = (uint32_t)((mb + ar) * 256);
    const uint32_t rowA1 = (uint32_t)((mb + 16 + ar) * 256);
    const uint32_t a_kl  = (uint32_t)((lane >> 4) << 4);
    const uint32_t rxA   = (uint32_t)(ar & 7) << 4;
    const int brr = (lane & 7) + ((lane >> 4) << 3);
    uint32_t rowB[2];
    #pragma unroll
    for (int nt = 0; nt < 2; ++nt)
        rowB[nt] = (uint32_t)((nbase + nt * 16 + brr) * 256);
    const uint32_t b_kl = (uint32_t)(((lane >> 3) & 1) << 4);
    const uint32_t rxB  = (uint32_t)(lane & 7) << 4;

    const float4 bs = __ldg((const float4*)bias + lane);

    // prologue gather of tile 0
    gather(base);

    #pragma unroll 1
    for (int it = 0; it < cnt; ++it) {
        asm volatile("cp.async.wait_group 0;" ::: "memory");
        __syncthreads();

        // ---- mainloop: 8 k-steps; terms A_hi*B_hi + A_hi*B_lo
        float d[2][4][4];
        #pragma unroll
        for (int mi = 0; mi < 2; ++mi)
            #pragma unroll
            for (int nq = 0; nq < 4; ++nq)
                #pragma unroll
                for (int j = 0; j < 4; ++j) d[mi][nq][j] = 0.f;

        {
            const uint32_t Ahi = sbase + SM_AD;
            const uint32_t Bhi = sbase + SM_B;
            const uint32_t Blo = sbase + SM_B + 32768;
            #pragma unroll
            for (int k0 = 0; k0 < 128; k0 += 16) {
                const uint32_t ka = ((uint32_t)(k0 * 2) + a_kl) ^ rxA;
                const uint32_t kb = ((uint32_t)(k0 * 2) + b_kl) ^ rxB;
                uint32_t ahi[2][4], bfr[4];
                ldm_x4(ahi[0], Ahi + rowA0 + ka);
                ldm_x4(ahi[1], Ahi + rowA1 + ka);
                #pragma unroll
                for (int nt = 0; nt < 2; ++nt) {
                    ldm_x4(bfr, Bhi + rowB[nt] + kb);
                    #pragma unroll
                    for (int mi = 0; mi < 2; ++mi) {
                        mma_f16(d[mi][nt * 2 + 0], ahi[mi], bfr + 0);
                        mma_f16(d[mi][nt * 2 + 1], ahi[mi], bfr + 2);
                    }
                    ldm_x4(bfr, Blo + rowB[nt] + kb);
                    #pragma unroll
                    for (int mi = 0; mi < 2; ++mi) {
                        mma_f16(d[mi][nt * 2 + 0], ahi[mi], bfr + 0);
                        mma_f16(d[mi][nt * 2 + 1], ahi[mi], bfr + 2);
                    }
                }
            }
        }
        __syncthreads();   // all ldmatrix A reads done before D overlays A

        // ---- stage D into AD region (pitch 512B, swizzled): 64 rows x 512B
        {
            const int g  = lane >> 2;
            const int c2 = (lane & 3) * 2;
            char* Dp = smem + SM_AD;
            #pragma unroll
            for (int mi = 0; mi < 2; ++mi) {
                #pragma unroll
                for (int nq = 0; nq < 4; ++nq) {
                    const int col = nbase + nq * 8 + c2;
                    const int r0  = mb + mi * 16 + g;
                    const uint32_t cb = (uint32_t)(col * 4);
                    uint32_t o0 = (uint32_t)(r0 * 512) + (cb ^ ((uint32_t)(r0 & 7) << 4));
                    uint32_t o1 = (uint32_t)((r0 + 8) * 512) + (cb ^ ((uint32_t)((r0 + 8) & 7) << 4));
                    *(float2*)(Dp + o0) = make_float2(d[mi][nq][0], d[mi][nq][1]);
                    *(float2*)(Dp + o1) = make_float2(d[mi][nq][2], d[mi][nq][3]);
                }
            }
        }
        __syncthreads();

        // ---- load routing acc regs (one pixel per warp), then free AD region
        float acc[8][4];
        {
            const char* Dp = smem + SM_AD;
            #pragma unroll
            for (int i = 0; i < 8; ++i) {
                const int row = wid * 8 + i;
                uint32_t off = (uint32_t)(row * 512)
                             + (((uint32_t)(lane * 16)) ^ ((uint32_t)(row & 7) << 4));
                float4 v = *(const float4*)(Dp + off);
                acc[i][0] = v.x; acc[i][1] = v.y; acc[i][2] = v.z; acc[i][3] = v.w;
            }
        }
        __syncthreads();   // all D reads done before AD region is re-gathered

        // ---- hoisted gather: cp.async latency hides under routing math
        if (it + 1 < cnt) gather(base + it + 1);

        // ---- routing math (registers + shuffles only)
        {
            float logits[8];
            float a0, a1, a2, a3;

            // iteration 0: softmax(0) == 0.125 exactly
            {
                float p0 = bs.x, p1 = bs.y, p2 = bs.z, p3 = bs.w;
                float s0 = 0.f, s1 = 0.f, s2 = 0.f, s3 = 0.f;
                #pragma unroll
                for (int i = 0; i < 8; ++i) {
                    s0 += acc[i][0]; s1 += acc[i][1];
                    s2 += acc[i][2]; s3 += acc[i][3];
                }
                p0 = fmaf(0.125f, s0, p0); p1 = fmaf(0.125f, s1, p1);
                p2 = fmaf(0.125f, s2, p2); p3 = fmaf(0.125f, s3, p3);
                float sq = p0 * p0 + p1 * p1 + p2 * p2 + p3 * p3;
                sq += __shfl_xor_sync(0xffffffffu, sq, 1);
                sq += __shfl_xor_sync(0xffffffffu, sq, 2);
                float scale = __fdividef(sq, 1.0f + sq) * rsqrtf(sq + 1e-9f);
                a0 = p0 * scale; a1 = p1 * scale; a2 = p2 * scale; a3 = p3 * scale;
                #pragma unroll
                for (int i = 0; i < 8; ++i) {
                    float dd = acc[i][0] * a0 + acc[i][1] * a1
                             + acc[i][2] * a2 + acc[i][3] * a3;
                    dd += __shfl_xor_sync(0xffffffffu, dd, 1);
                    dd += __shfl_xor_sync(0xffffffffu, dd, 2);
                    logits[i] = dd;
                }
            }

            // iterations 1,2: softmax without max-sub (|logits| small)
            #pragma unroll
            for (int itr = 1; itr < 3; ++itr) {
                float r[8];
                #pragma unroll
                for (int i = 0; i < 8; ++i) {
                    float e = __expf(logits[i]);
                    float ss = e;
                    ss += __shfl_xor_sync(0xffffffffu, ss, 4);
                    ss += __shfl_xor_sync(0xffffffffu, ss, 8);
                    ss += __shfl_xor_sync(0xffffffffu, ss, 16);
                    r[i] = __fdividef(e, ss);
                }
                float p0 = bs.x, p1 = bs.y, p2 = bs.z, p3 = bs.w;
                #pragma unroll
                for (int i = 0; i < 8; ++i) {
                    p0 = fmaf(r[i], acc[i][0], p0);
                    p1 = fmaf(r[i], acc[i][1], p1);
                    p2 = fmaf(r[i], acc[i][2], p2);
                    p3 = fmaf(r[i], acc[i][3], p3);
                }
                float sq = p0 * p0 + p1 * p1 + p2 * p2 + p3 * p3;
                sq += __shfl_xor_sync(0xffffffffu, sq, 1);
                sq += __shfl_xor_sync(0xffffffffu, sq, 2);
                float scale = __fdividef(sq, 1.0f + sq) * rsqrtf(sq + 1e-9f);
                a0 = p0 * scale; a1 = p1 * scale; a2 = p2 * scale; a3 = p3 * scale;

                if (itr == 1) {
                    #pragma unroll
                    for (int i = 0; i < 8; ++i) {
                        float dd = acc[i][0] * a0 + acc[i][1] * a1
                                 + acc[i][2] * a2 + acc[i][3] * a3;
                        dd += __shfl_xor_sync(0xffffffffu, dd, 1);
                        dd += __shfl_xor_sync(0xffffffffu, dd, 2);
                        logits[i] += dd;
                    }
                }
            }

            const int P   = (base + it) * 8 + wid;
            const int b   = P / 3136;
            const int rem = P - b * 3136;
            const int hh  = rem / 56, ww = rem - (rem / 56) * 56;
            const int h   = hpar + 2 * hh;
            const int w   = wpar + 2 * ww;
            ((float4*)out)[(size_t)((b * HP + h) * WP + w) * 32 + lane]
                = make_float4(a0, a1, a2, a3);
        }
    }
}

extern "C" void kernel_launch(void* const* d_in, const int* in_sizes, int n_in,
                              void* d_out, int out_size) {
    const float* x = nullptr;
    const float* W = nullptr;
    const float* bias = nullptr;
    for (int i = 0; i < n_in; ++i) {
        if (in_sizes[i] == XN)                    x    = (const float*)d_in[i];
        else if (in_sizes[i] == 4 * 4 * 128 * 32) W    = (const float*)d_in[i];
        else if (in_sizes[i] == 128)              bias = (const float*)d_in[i];
    }
    float* out = (float*)d_out;

    cudaFuncSetAttribute(deconv_caps_pers_kernel,
                         cudaFuncAttributeMaxDynamicSharedMemorySize, SMEM_TOTAL);

    prep_kernel<<<(XN + 255) / 256, 256>>>(W, x);

    dim3 grid(NBLK, 4);
    deconv_caps_pers_kernel<<<grid, 256, SMEM_TOTAL>>>(bias, out);
}